// round 11
// baseline (speedup 1.0000x reference)
#include <cuda_runtime.h>
#include <cuda_fp16.h>
#include <math.h>
#include <stdint.h>

#define Bn 4096
#define HSLOT ((size_t)Bn * 512)
#define STAGE_BYTES 36864
#define SMEM_BYTES (2 * STAGE_BYTES)

// Gate permutation: physical col p (p<2048) <-> logical (gate g, unit j):
//   g = (p>>3)&3, j = ((p>>5)<<3) + (p&7)

// ---------------- device scratch ----------------
__device__ __half g_Ah[(size_t)17 * HSLOT];
__device__ __half g_APRE[(size_t)65536 * 64];
__device__ __half g_WTb[(size_t)2560 * 512];
__device__ __half g_WPRE[(size_t)2560 * 64];
__device__ __half g_WT2[1024 * 512];
__device__ __half g_WT3[512 * 512];
__device__ __half g_WTh[256 * 512];
__device__ __half g_ZX16[(size_t)16 * Bn * 2048];
__device__ __half g_TG16[(size_t)16 * Bn * 512];
__device__ __half g_MEMA16[(size_t)15 * HSLOT];
__device__ __half g_HcH[(size_t)Bn * 512];
__device__ __half g_HBh[(size_t)Bn * 512];
__device__ __half g_HGh[(size_t)Bn * 512];
__device__ __half g_CXH[(size_t)Bn * 512];
__device__ float g_C[(size_t)Bn * 512];
__device__ float g_HD1[(size_t)Bn * 256];
__device__ float g_HD2[(size_t)Bn * 32];
__device__ float g_s[512];
__device__ float g_sA[512];

// grid barrier state
__device__ unsigned g_bar_arrive;
__device__ volatile unsigned g_bar_gen;

__device__ __forceinline__ float sigm(float x) { return 1.f / (1.f + expf(-x)); }
__device__ __forceinline__ float sigmf_(float x) { return __fdividef(1.f, 1.f + __expf(-x)); }
__device__ __forceinline__ float tanh_app(float x) {
    float y; asm("tanh.approx.f32 %0, %1;" : "=f"(y) : "f"(x)); return y;
}
__device__ __forceinline__ uint32_t smem_u32(const void* p) {
    uint32_t a;
    asm("{ .reg .u64 t; cvta.to.shared.u64 t, %1; cvt.u32.u64 %0, t; }" : "=r"(a) : "l"(p));
    return a;
}
__device__ __forceinline__ void ldm4(uint32_t* r, uint32_t a) {
    asm volatile("ldmatrix.sync.aligned.m8n8.x4.shared.b16 {%0,%1,%2,%3}, [%4];"
                 : "=r"(r[0]), "=r"(r[1]), "=r"(r[2]), "=r"(r[3]) : "r"(a));
}
__device__ __forceinline__ void mma16816(float* c, const uint32_t* a, uint32_t b0, uint32_t b1) {
    asm volatile("mma.sync.aligned.m16n8k16.row.col.f32.f16.f16.f32 "
                 "{%0,%1,%2,%3}, {%4,%5,%6,%7}, {%8,%9}, {%0,%1,%2,%3};"
                 : "+f"(c[0]), "+f"(c[1]), "+f"(c[2]), "+f"(c[3])
                 : "r"(a[0]), "r"(a[1]), "r"(a[2]), "r"(a[3]), "r"(b0), "r"(b1));
}
__device__ __forceinline__ void cp16(uint32_t saddr, const void* gptr) {
    asm volatile("cp.async.cg.shared.global [%0], [%1], 16;"
                 :: "r"(saddr), "l"(__cvta_generic_to_global(gptr)) : "memory");
}
__device__ __forceinline__ void cp_commit() {
    asm volatile("cp.async.commit_group;" ::: "memory");
}

__device__ __forceinline__ void grid_bar(int nCTA) {
    __syncthreads();
    if (threadIdx.x == 0) {
        __threadfence();
        unsigned gen = g_bar_gen;
        if (atomicAdd(&g_bar_arrive, 1u) == (unsigned)(nCTA - 1)) {
            g_bar_arrive = 0;
            __threadfence();
            g_bar_gen = gen + 1;
        } else {
            while (g_bar_gen == gen) __nanosleep(64);
        }
        __threadfence();
    }
    __syncthreads();
}

// ---------------- prep kernels ----------------
__global__ void prep_weights(const float* __restrict__ Uh, const float* __restrict__ Wx,
                             const float* __restrict__ Wt, const float* __restrict__ Wa,
                             const float* __restrict__ WxT, const float* __restrict__ Wb,
                             const float* __restrict__ Wg, const float* __restrict__ We,
                             const float* __restrict__ W1) {
    int stride = gridDim.x * blockDim.x;
    int t0 = blockIdx.x * blockDim.x + threadIdx.x;
    for (int i = t0; i < 2560 * 512; i += stride) {
        int n = i >> 9, k = i & 511;
        float w;
        if (n < 2048) {
            int g = (n >> 3) & 3, j = ((n >> 5) << 3) + (n & 7);
            w = Uh[(size_t)k * 2048 + g * 512 + j];
        } else {
            w = Wa[(size_t)k * 512 + (n - 2048)];
        }
        g_WTb[i] = __float2half(w);
    }
    for (int i = t0; i < 2560 * 64; i += stride) {
        int n = i >> 6, k = i & 63;
        float w;
        if (n < 2048) {
            int g = (n >> 3) & 3, j = ((n >> 5) << 3) + (n & 7);
            if (k < 63) w = Wx[(size_t)k * 2048 + g * 512 + j];
            else        w = (g < 3) ? Wt[g * 512 + j] : 0.f;
        } else {
            w = (k < 63) ? WxT[(size_t)k * 512 + (n - 2048)] : 0.f;
        }
        g_WPRE[i] = __float2half(w);
    }
    for (int i = t0; i < 1024 * 512; i += stride) {
        int n = i >> 9, k = i & 511;
        float w = (n < 512) ? Wb[(size_t)k * 512 + n] : Wg[(size_t)k * 512 + (n - 512)];
        g_WT2[i] = __float2half(w);
    }
    for (int i = t0; i < 512 * 512; i += stride) {
        int n = i >> 9, k = i & 511;
        g_WT3[i] = __float2half(We[(size_t)k * 512 + n]);
    }
    for (int i = t0; i < 256 * 512; i += stride) {
        int n = i >> 9, k = i & 511;
        g_WTh[i] = __float2half(W1[(size_t)k * 256 + n]);
    }
}

__global__ void prep_s(const float* __restrict__ init_proj) {
    int h = threadIdx.x;
    float s = 0.f;
    for (int f = 0; f < 64; ++f) s += init_proj[f * 512 + h];
    g_s[h] = s;
}

__global__ void prep_sA(const float* __restrict__ Wa) {
    int h = threadIdx.x;
    float acc = 0.f;
    for (int k = 0; k < 512; ++k) acc += g_s[k] * Wa[k * 512 + h];
    g_sA[h] = acc;
}

__global__ void prep_A(const float* __restrict__ inp) {
    int stride = gridDim.x * blockDim.x;
    int t0 = blockIdx.x * blockDim.x + threadIdx.x;
    for (int i = t0; i < 65536 * 64; i += stride) {
        int r = i >> 6, k = i & 63;
        float v = (k < 63) ? inp[(size_t)r * 64 + 1 + k] : inp[(size_t)r * 64];
        g_APRE[i] = __float2half(v);
    }
}

// ---------------- GEMM tile as device function (MODE 1/2/3) ----------------
template <int MODE>
__device__ void gemm_tile(char* smem, int m0, int n0,
                          const __half* __restrict__ A, int K,
                          const __half* __restrict__ Bh,
                          const float* __restrict__ e0, const float* __restrict__ e1,
                          const __half* __restrict__ e0h,
                          __half* __restrict__ o2h, __half* __restrict__ oh,
                          const __half* __restrict__ zxp, const __half* __restrict__ tgp,
                          float* __restrict__ Cp) {
    uint32_t sb = smem_u32(smem);
    const int tid = threadIdx.x;
    const int lane = tid & 31, wid = tid >> 5;
    const int wm = wid & 1, wn = wid >> 1;
    const int gid = lane >> 2, tq = lane & 3;
    const int kch = K >> 6;

    float acc[4][4][4];
    #pragma unroll
    for (int a = 0; a < 4; ++a)
        #pragma unroll
        for (int b2 = 0; b2 < 4; ++b2)
            #pragma unroll
            for (int c = 0; c < 4; ++c) acc[a][b2][c] = 0.f;

    auto copy_chunk = [&](int ch, int s) {
        int kc = ch << 6;
        uint32_t base = sb + s * STAGE_BYTES;
        #pragma unroll
        for (int i = 0; i < 4; ++i) {
            int lin = tid + (i << 8);
            int r = lin >> 3;
            int c16 = (lin & 7) << 4;
            cp16(base + r * 144 + c16,
                 (const char*)(A + (size_t)(m0 + r) * K + kc) + c16);
            cp16(base + 18432 + r * 144 + c16,
                 (const char*)(Bh + (size_t)(n0 + r) * K + kc) + c16);
        }
    };

    copy_chunk(0, 0);
    cp_commit();

    const int arow = wm * 64 + (lane & 15);
    const int acol = (lane >> 4) << 4;
    const int brow = wn * 32 + (lane & 7) + ((lane >> 4) << 3);
    const int bcol = ((lane >> 3) & 1) << 4;

    for (int ch = 0; ch < kch; ++ch) {
        if (ch + 1 < kch) {
            copy_chunk(ch + 1, (ch + 1) & 1);
            cp_commit();
            asm volatile("cp.async.wait_group 1;" ::: "memory");
        } else {
            asm volatile("cp.async.wait_group 0;" ::: "memory");
        }
        __syncthreads();

        uint32_t abase = sb + (ch & 1) * STAGE_BYTES;
        uint32_t bbase = abase + 18432;
        #pragma unroll
        for (int k16 = 0; k16 < 4; ++k16) {
            int kb = k16 << 5;
            uint32_t bf[2][4];
            #pragma unroll
            for (int ni2 = 0; ni2 < 2; ++ni2)
                ldm4(bf[ni2], bbase + (brow + ni2 * 16) * 144 + kb + bcol);
            uint32_t af[4][4];
            #pragma unroll
            for (int mi = 0; mi < 4; ++mi)
                ldm4(af[mi], abase + (arow + mi * 16) * 144 + kb + acol);
            #pragma unroll
            for (int ni2 = 0; ni2 < 2; ++ni2)
                #pragma unroll
                for (int mi = 0; mi < 4; ++mi) {
                    mma16816(acc[mi][ni2 * 2],     af[mi], bf[ni2][0], bf[ni2][1]);
                    mma16816(acc[mi][ni2 * 2 + 1], af[mi], bf[ni2][2], bf[ni2][3]);
                }
        }
        __syncthreads();
    }

    if (MODE == 1) {
        if (n0 < 2048) {
            int blk = (n0 + wn * 32) >> 5;
            int j = blk * 8 + (tq << 1);
            #pragma unroll
            for (int mi = 0; mi < 4; ++mi) {
                int mb = m0 + wm * 64 + mi * 16 + gid;
                #pragma unroll
                for (int hf = 0; hf < 2; ++hf) {
                    int r = mb + hf * 8;
                    int ko = hf * 2;
                    const __half* zxr = zxp + (size_t)r * 2048 + blk * 32 + (tq << 1);
                    float2 xi = __half22float2(*(const __half2*)(zxr));
                    float2 xf = __half22float2(*(const __half2*)(zxr + 8));
                    float2 xo = __half22float2(*(const __half2*)(zxr + 16));
                    float2 xc = __half22float2(*(const __half2*)(zxr + 24));
                    float2 tg2 = __half22float2(*(const __half2*)(tgp + (size_t)r * 512 + j));
                    float2 cold = *(float2*)(Cp + (size_t)r * 512 + j);
                    float ch0 = tanh_app(acc[mi][3][ko] + xc.x);
                    float ch1 = tanh_app(acc[mi][3][ko + 1] + xc.y);
                    float c0 = fmaf(sigmf_(acc[mi][1][ko] + xf.x), cold.x,
                                    (sigmf_(acc[mi][0][ko] + xi.x) + tg2.x) * ch0);
                    float c1 = fmaf(sigmf_(acc[mi][1][ko + 1] + xf.y), cold.y,
                                    (sigmf_(acc[mi][0][ko + 1] + xi.y) + tg2.y) * ch1);
                    *(float2*)(Cp + (size_t)r * 512 + j) = make_float2(c0, c1);
                    float h0 = sigmf_(acc[mi][2][ko] + xo.x) * tanh_app(c0);
                    float h1 = sigmf_(acc[mi][2][ko + 1] + xo.y) * tanh_app(c1);
                    *(__half2*)(oh + (size_t)r * 512 + j) = __floats2half2_rn(h0, h1);
                }
            }
        } else {
            #pragma unroll
            for (int mi = 0; mi < 4; ++mi)
                #pragma unroll
                for (int ni = 0; ni < 4; ++ni) {
                    float* cc = acc[mi][ni];
                    int m = m0 + wm * 64 + mi * 16 + gid;
                    int c = n0 + wn * 32 + ni * 8 + (tq << 1) - 2048;
                    *(__half2*)(o2h + (size_t)m * 512 + c) = __floats2half2_rn(cc[0], cc[1]);
                    *(__half2*)(o2h + (size_t)(m + 8) * 512 + c) = __floats2half2_rn(cc[2], cc[3]);
                }
        }
        return;
    }

    #pragma unroll
    for (int mi = 0; mi < 4; ++mi) {
        #pragma unroll
        for (int ni = 0; ni < 4; ++ni) {
            float* cc = acc[mi][ni];
            int m = m0 + wm * 64 + mi * 16 + gid;
            int c = n0 + wn * 32 + ni * 8 + (tq << 1);
            if (MODE == 2) {
                if (c < 512) {
                    float b0 = e0[c], b1 = e0[c + 1];
                    *(__half2*)(o2h + (size_t)m * 512 + c) = __floats2half2_rn(cc[0] + b0, cc[1] + b1);
                    *(__half2*)(o2h + (size_t)(m + 8) * 512 + c) = __floats2half2_rn(cc[2] + b0, cc[3] + b1);
                } else {
                    int cj = c - 512;
                    *(__half2*)(oh + (size_t)m * 512 + cj) = __floats2half2_rn(cc[0], cc[1]);
                    *(__half2*)(oh + (size_t)(m + 8) * 512 + cj) = __floats2half2_rn(cc[2], cc[3]);
                }
            } else {  // MODE 3
                float b0 = e1[c], b1 = e1[c + 1];
                float2 hg0 = __half22float2(*(const __half2*)(e0h + (size_t)m * 512 + c));
                float2 hg1 = __half22float2(*(const __half2*)(e0h + (size_t)(m + 8) * 512 + c));
                *(__half2*)(oh + (size_t)m * 512 + c) =
                    __floats2half2_rn(tanh_app(cc[0] + hg0.x + b0), tanh_app(cc[1] + hg0.y + b1));
                *(__half2*)(oh + (size_t)(m + 8) * 512 + c) =
                    __floats2half2_rn(tanh_app(cc[2] + hg1.x + b0), tanh_app(cc[3] + hg1.y + b1));
            }
        }
    }
}

// ---------------- attention row (device) ----------------
__device__ void attn_row(char* smem, int b, int t, const float* __restrict__ va) {
    float* sred = (float*)smem;          // 15*8
    float* se = (float*)smem + 120;      // 15
    int tid = threadIdx.x;
    float2 hb = __half22float2(((const __half2*)(g_HBh + (size_t)b * 512))[tid]);
    float2 va2 = *(const float2*)(va + 2 * tid);
    float2 sA2 = *(const float2*)(g_sA + 2 * tid);
    float2 s2  = *(const float2*)(g_s + 2 * tid);
    int lane = tid & 31, wp = tid >> 5;

    #pragma unroll
    for (int d = 0; d < 15; ++d) {
        int j = t - 15 + d;
        float m0, m1;
        if (j < 0) { m0 = sA2.x; m1 = sA2.y; }
        else {
            float2 f = __half22float2(
                ((const __half2*)(g_MEMA16 + (size_t)j * HSLOT + (size_t)b * 512))[tid]);
            m0 = f.x; m1 = f.y;
        }
        float s = va2.x * tanh_app(m0 + hb.x) + va2.y * tanh_app(m1 + hb.y);
        #pragma unroll
        for (int off = 16; off; off >>= 1) s += __shfl_xor_sync(0xffffffffu, s, off);
        if (lane == 0) sred[d * 8 + wp] = s;
    }
    __syncthreads();
    if (tid < 15) {
        float e = 0.f;
        #pragma unroll
        for (int w2 = 0; w2 < 8; ++w2) e += sred[tid * 8 + w2];
        se[tid] = e;
    }
    __syncthreads();

    float mx = -1e30f;
    #pragma unroll
    for (int d = 0; d < 15; ++d) mx = fmaxf(mx, se[d]);
    float al[15], sum = 0.f;
    #pragma unroll
    for (int d = 0; d < 15; ++d) { al[d] = __expf(se[d] - mx); sum += al[d]; }
    float inv = __fdividef(1.f, sum);
    float c0 = 0.f, c1 = 0.f;
    #pragma unroll
    for (int d = 0; d < 15; ++d) {
        int j = t - 15 + d;
        float a = al[d] * inv;
        float m0, m1;
        if (j < 0) { m0 = s2.x; m1 = s2.y; }
        else {
            float2 f = __half22float2(
                ((const __half2*)(g_Ah + (size_t)(j + 1) * HSLOT + (size_t)b * 512))[tid]);
            m0 = f.x; m1 = f.y;
        }
        c0 = fmaf(a, m0, c0);
        c1 = fmaf(a, m1, c1);
    }
    ((__half2*)(g_CXH + (size_t)b * 512))[tid] = __floats2half2_rn(c0, c1);
    __syncthreads();
}

// ---------------- persistent recurrence kernel ----------------
__global__ __launch_bounds__(256, 2)
void recur_k(int nCTA, const float* __restrict__ va, const float* __restrict__ ba,
             const float* __restrict__ bhv) {
    extern __shared__ char smem[];
    for (int t = 0; t < 16; ++t) {
        // ---- phase A: MODE1 (t>0) or t=0 gates ----
        if (t == 0) {
            for (int idx = blockIdx.x * 256 + threadIdx.x; idx < Bn * 512; idx += nCTA * 256) {
                int b = idx >> 9, j = idx & 511;
                int blk = j >> 3, jr = j & 7;
                const __half* zx = g_ZX16 + (size_t)b * 2048 + blk * 32 + jr;
                float zi = __half2float(zx[0]);
                float zo = __half2float(zx[16]);
                float zc = __half2float(zx[24]);
                float tg = __half2float(g_TG16[idx]);
                float ch = tanh_app(zc);
                float c = (sigmf_(zi) + tg) * ch;
                g_C[idx] = c;
                g_HcH[idx] = __float2half(sigmf_(zo) * tanh_app(c));
            }
        } else {
            const __half* A = g_Ah + (size_t)t * HSLOT;
            const __half* zxp = g_ZX16 + (size_t)t * Bn * 2048;
            const __half* tgp = g_TG16 + (size_t)t * Bn * 512;
            __half* mema = g_MEMA16 + (size_t)(t - 1) * HSLOT;
            for (int tile = blockIdx.x; tile < 640; tile += nCTA) {
                int nt = tile % 20, mt = tile / 20;
                gemm_tile<1>(smem, mt * 128, nt * 128, A, 512, g_WTb,
                             nullptr, nullptr, nullptr, mema, g_HcH, zxp, tgp, g_C);
            }
        }
        grid_bar(nCTA);

        // ---- phase B: MODE2 ----
        for (int tile = blockIdx.x; tile < 256; tile += nCTA) {
            int nt = tile % 8, mt = tile / 8;
            gemm_tile<2>(smem, mt * 128, nt * 128, g_HcH, 512, g_WT2,
                         ba, nullptr, nullptr, g_HBh, g_HGh, nullptr, nullptr, nullptr);
        }
        grid_bar(nCTA);

        // ---- phase C: attention ----
        for (int b = blockIdx.x; b < Bn; b += nCTA)
            attn_row(smem, b, t, va);
        grid_bar(nCTA);

        // ---- phase D: MODE3 ----
        {
            __half* dst = g_Ah + (size_t)(t + 1) * HSLOT;
            for (int tile = blockIdx.x; tile < 128; tile += nCTA) {
                int nt = tile % 4, mt = tile / 4;
                gemm_tile<3>(smem, mt * 128, nt * 128, g_CXH, 512, g_WT3,
                             nullptr, bhv, g_HGh, nullptr, dst, nullptr, nullptr, nullptr);
            }
        }
        grid_bar(nCTA);
    }
}

// ---------------- standalone GEMM for MODE 4 (head) and MODE 5 (pre) ----------------
template <int MODE>
__global__ __launch_bounds__(256, 2)
void mma_gemm(const __half* __restrict__ A, int lda, int K,
              const __half* __restrict__ Bh,
              const float* __restrict__ e0, float* __restrict__ o0,
              const float* __restrict__ inp, const float* __restrict__ WtT,
              const float* __restrict__ bT) {
    extern __shared__ char smem[];
    uint32_t sb = smem_u32(smem);
    const int tid = threadIdx.x;
    const int lane = tid & 31, wid = tid >> 5;
    const int wm = wid & 1, wn = wid >> 1;
    const int gid = lane >> 2, tq = lane & 3;
    const int m0 = blockIdx.y * 128, n0 = blockIdx.x * 128;
    const int kch = K >> 6;

    float acc[4][4][4];
    #pragma unroll
    for (int a = 0; a < 4; ++a)
        #pragma unroll
        for (int b2 = 0; b2 < 4; ++b2)
            #pragma unroll
            for (int c = 0; c < 4; ++c) acc[a][b2][c] = 0.f;

    auto copy_chunk = [&](int ch, int s) {
        int kc = ch << 6;
        uint32_t base = sb + s * STAGE_BYTES;
        #pragma unroll
        for (int i = 0; i < 4; ++i) {
            int lin = tid + (i << 8);
            int r = lin >> 3;
            int c16 = (lin & 7) << 4;
            cp16(base + r * 144 + c16,
                 (const char*)(A + (size_t)(m0 + r) * lda + kc) + c16);
            cp16(base + 18432 + r * 144 + c16,
                 (const char*)(Bh + (size_t)(n0 + r) * K + kc) + c16);
        }
    };

    copy_chunk(0, 0);
    cp_commit();

    const int arow = wm * 64 + (lane & 15);
    const int acol = (lane >> 4) << 4;
    const int brow = wn * 32 + (lane & 7) + ((lane >> 4) << 3);
    const int bcol = ((lane >> 3) & 1) << 4;

    for (int ch = 0; ch < kch; ++ch) {
        if (ch + 1 < kch) {
            copy_chunk(ch + 1, (ch + 1) & 1);
            cp_commit();
            asm volatile("cp.async.wait_group 1;" ::: "memory");
        } else {
            asm volatile("cp.async.wait_group 0;" ::: "memory");
        }
        __syncthreads();

        uint32_t abase = sb + (ch & 1) * STAGE_BYTES;
        uint32_t bbase = abase + 18432;
        #pragma unroll
        for (int k16 = 0; k16 < 4; ++k16) {
            int kb = k16 << 5;
            uint32_t bf[2][4];
            #pragma unroll
            for (int ni2 = 0; ni2 < 2; ++ni2)
                ldm4(bf[ni2], bbase + (brow + ni2 * 16) * 144 + kb + bcol);
            uint32_t af[4][4];
            #pragma unroll
            for (int mi = 0; mi < 4; ++mi)
                ldm4(af[mi], abase + (arow + mi * 16) * 144 + kb + acol);
            #pragma unroll
            for (int ni2 = 0; ni2 < 2; ++ni2)
                #pragma unroll
                for (int mi = 0; mi < 4; ++mi) {
                    mma16816(acc[mi][ni2 * 2],     af[mi], bf[ni2][0], bf[ni2][1]);
                    mma16816(acc[mi][ni2 * 2 + 1], af[mi], bf[ni2][2], bf[ni2][3]);
                }
        }
        __syncthreads();
    }

    auto epi = [&](int m, int c, float x, float y) {
        if (MODE == 4) {
            *(float2*)(o0 + (size_t)m * 256 + c) =
                make_float2(fmaxf(x + e0[c], 0.f), fmaxf(y + e0[c + 1], 0.f));
        } else {  // MODE 5
            int b_ = m >> 4, t_ = m & 15;
            size_t zr = (size_t)t_ * Bn + b_;
            if (c < 2048) {
                int g = (c >> 3) & 3;
                int j0 = ((c >> 5) << 3) + (c & 7);
                *(__half2*)(g_ZX16 + zr * 2048 + c) =
                    __floats2half2_rn(x + e0[g * 512 + j0], y + e0[g * 512 + j0 + 1]);
            } else {
                int j = c - 2048;
                float tv = inp[(size_t)m * 64];
                float t0v = sigm(x + sigm(tv * WtT[j]) + bT[j]);
                float t1v = sigm(y + sigm(tv * WtT[j + 1]) + bT[j + 1]);
                *(__half2*)(g_TG16 + zr * 512 + j) = __floats2half2_rn(t0v, t1v);
            }
        }
    };

    #pragma unroll
    for (int mi = 0; mi < 4; ++mi) {
        #pragma unroll
        for (int ni = 0; ni < 4; ++ni) {
            float* cc = acc[mi][ni];
            int m = m0 + wm * 64 + mi * 16 + gid;
            int c = n0 + wn * 32 + ni * 8 + (tq << 1);
            epi(m, c, cc[0], cc[1]);
            epi(m + 8, c, cc[2], cc[3]);
        }
    }
}

// ---------------- head layers 2,3 ----------------
__global__ void head2_k(const float* __restrict__ HD1, const float* __restrict__ W2,
                        const float* __restrict__ b2, float* __restrict__ HD2) {
    int warp = (blockIdx.x * blockDim.x + threadIdx.x) >> 5;
    int lane = threadIdx.x & 31;
    if (warp >= Bn) return;
    const float* h = HD1 + (size_t)warp * 256;
    float acc = 0.f;
    for (int k = 0; k < 256; ++k) acc = fmaf(h[k], W2[k * 32 + lane], acc);
    HD2[(size_t)warp * 32 + lane] = fmaxf(acc + b2[lane], 0.f);
}

__global__ void head3_k(const float* __restrict__ HD2, const float* __restrict__ W3,
                        const float* __restrict__ b3, float* __restrict__ out) {
    int b = blockIdx.x * blockDim.x + threadIdx.x;
    if (b >= Bn) return;
    float a0 = b3[0], a1 = b3[1];
    const float* h = HD2 + (size_t)b * 32;
    #pragma unroll
    for (int k = 0; k < 32; ++k) {
        float hv = h[k];
        a0 = fmaf(hv, W3[k * 2 + 0], a0);
        a1 = fmaf(hv, W3[k * 2 + 1], a1);
    }
    float m = fmaxf(a0, a1);
    float e0v = expf(a0 - m), e1v = expf(a1 - m);
    float inv = 1.f / (e0v + e1v);
    out[(size_t)b * 2 + 0] = e0v * inv;
    out[(size_t)b * 2 + 1] = e1v * inv;
}

// ---------------- launcher ----------------
extern "C" void kernel_launch(void* const* d_in, const int* in_sizes, int n_in,
                              void* d_out, int out_size) {
    const float* inputs    = (const float*)d_in[0];
    const float* init_proj = (const float*)d_in[1];
    const float* Wx  = (const float*)d_in[3];
    const float* Uh  = (const float*)d_in[4];
    const float* Wt  = (const float*)d_in[5];
    const float* b   = (const float*)d_in[6];
    const float* WxT = (const float*)d_in[7];
    const float* WtT = (const float*)d_in[8];
    const float* bT  = (const float*)d_in[9];
    const float* Wa  = (const float*)d_in[10];
    const float* Wb  = (const float*)d_in[11];
    const float* va  = (const float*)d_in[12];
    const float* ba  = (const float*)d_in[13];
    const float* We  = (const float*)d_in[14];
    const float* Wg  = (const float*)d_in[15];
    const float* bh  = (const float*)d_in[16];
    const float* W1  = (const float*)d_in[17];
    const float* b1  = (const float*)d_in[18];
    const float* W2  = (const float*)d_in[19];
    const float* b2  = (const float*)d_in[20];
    const float* W3  = (const float*)d_in[21];
    const float* b3  = (const float*)d_in[22];
    float* out = (float*)d_out;

    cudaFuncSetAttribute(recur_k, cudaFuncAttributeMaxDynamicSharedMemorySize, SMEM_BYTES);
    cudaFuncSetAttribute(mma_gemm<4>, cudaFuncAttributeMaxDynamicSharedMemorySize, SMEM_BYTES);
    cudaFuncSetAttribute(mma_gemm<5>, cudaFuncAttributeMaxDynamicSharedMemorySize, SMEM_BYTES);

    int smcount = 148;
    cudaDeviceGetAttribute(&smcount, cudaDevAttrMultiProcessorCount, 0);
    int maxb = 0;
    cudaOccupancyMaxActiveBlocksPerMultiprocessor(&maxb, recur_k, 256, SMEM_BYTES);
    if (maxb < 1) maxb = 1;
    int nCTA = smcount * (maxb >= 2 ? 2 : 1);

    __half *APRE, *WPRE, *Ah, *WTh;
    float *HD1, *HD2;
    cudaGetSymbolAddress((void**)&APRE, g_APRE);
    cudaGetSymbolAddress((void**)&WPRE, g_WPRE);
    cudaGetSymbolAddress((void**)&Ah, g_Ah);
    cudaGetSymbolAddress((void**)&WTh, g_WTh);
    cudaGetSymbolAddress((void**)&HD1, g_HD1);
    cudaGetSymbolAddress((void**)&HD2, g_HD2);

    prep_weights<<<1024, 256>>>(Uh, Wx, Wt, Wa, WxT, Wb, Wg, We, W1);
    prep_s<<<1, 512>>>(init_proj);
    prep_sA<<<1, 512>>>(Wa);
    prep_A<<<2048, 256>>>(inputs);

    // pre-GEMM: ZX(perm) + TG for all steps
    mma_gemm<5><<<dim3(20, 512), 256, SMEM_BYTES>>>(
        APRE, 64, 64, WPRE, b, nullptr, inputs, WtT, bT);

    // full 16-step recurrence in one persistent kernel
    recur_k<<<nCTA, 256, SMEM_BYTES>>>(nCTA, va, ba, bh);

    mma_gemm<4><<<dim3(2, 32), 256, SMEM_BYTES>>>(
        Ah + (size_t)16 * HSLOT, 512, 512, WTh, b1, HD1, nullptr, nullptr, nullptr);
    head2_k<<<512, 256>>>(HD1, W2, b2, HD2);
    head3_k<<<16, 256>>>(HD2, W3, b3, out);
}

// round 12
// speedup vs baseline: 1.3112x; 1.3112x over previous
#include <cuda_runtime.h>
#include <cuda_fp16.h>
#include <math.h>
#include <stdint.h>

#define Bn 4096
#define HSLOT ((size_t)Bn * 512)
#define STAGE_BYTES 36864
#define SMEM_BYTES (2 * STAGE_BYTES)

// Gate permutation: physical col p (p<2048) <-> logical (gate g, unit j):
//   g = (p>>3)&3, j = ((p>>5)<<3) + (p&7)

// ---------------- device scratch ----------------
__device__ __half g_Ah[(size_t)17 * HSLOT];         // slot j+1 holds h_j (fp16); slot 0 unused
__device__ __half g_APRE[(size_t)65536 * 64];
__device__ __half g_WTb[(size_t)2560 * 512];        // [Uh(perm) | Wa], n-major
__device__ __half g_WPRE[(size_t)2560 * 64];
__device__ __half g_WT2[1024 * 512];
__device__ __half g_WT3[512 * 512];
__device__ __half g_WTh[256 * 512];
__device__ __half g_ZX16[(size_t)16 * Bn * 2048];
__device__ __half g_TG16[(size_t)16 * Bn * 512];
__device__ __half g_MEMA16[(size_t)15 * HSLOT];
__device__ __half g_HcH[(size_t)Bn * 512];
__device__ __half g_HBh[(size_t)Bn * 512];
__device__ __half g_HGh[(size_t)Bn * 512];
__device__ __half g_CXH[(size_t)Bn * 512];
__device__ float g_C[(size_t)Bn * 512];
__device__ float g_HD1[(size_t)Bn * 256];
__device__ float g_HD2[(size_t)Bn * 32];
__device__ float g_s[512];
__device__ float g_sA[512];

__device__ __forceinline__ float sigm(float x) { return 1.f / (1.f + expf(-x)); }
__device__ __forceinline__ float sigmf_(float x) { return __fdividef(1.f, 1.f + __expf(-x)); }
__device__ __forceinline__ float tanh_app(float x) {
    float y; asm("tanh.approx.f32 %0, %1;" : "=f"(y) : "f"(x)); return y;
}

__device__ __forceinline__ uint32_t smem_u32(const void* p) {
    uint32_t a;
    asm("{ .reg .u64 t; cvta.to.shared.u64 t, %1; cvt.u32.u64 %0, t; }" : "=r"(a) : "l"(p));
    return a;
}
__device__ __forceinline__ void ldm4(uint32_t* r, uint32_t a) {
    asm volatile("ldmatrix.sync.aligned.m8n8.x4.shared.b16 {%0,%1,%2,%3}, [%4];"
                 : "=r"(r[0]), "=r"(r[1]), "=r"(r[2]), "=r"(r[3]) : "r"(a));
}
__device__ __forceinline__ void mma16816(float* c, const uint32_t* a, uint32_t b0, uint32_t b1) {
    asm volatile("mma.sync.aligned.m16n8k16.row.col.f32.f16.f16.f32 "
                 "{%0,%1,%2,%3}, {%4,%5,%6,%7}, {%8,%9}, {%0,%1,%2,%3};"
                 : "+f"(c[0]), "+f"(c[1]), "+f"(c[2]), "+f"(c[3])
                 : "r"(a[0]), "r"(a[1]), "r"(a[2]), "r"(a[3]), "r"(b0), "r"(b1));
}
__device__ __forceinline__ void cp16(uint32_t saddr, const void* gptr) {
    asm volatile("cp.async.cg.shared.global [%0], [%1], 16;"
                 :: "r"(saddr), "l"(__cvta_generic_to_global(gptr)) : "memory");
}
__device__ __forceinline__ void cp_commit() {
    asm volatile("cp.async.commit_group;" ::: "memory");
}

// ---------------- prep kernels ----------------
__global__ void prep_weights(const float* __restrict__ Uh, const float* __restrict__ Wx,
                             const float* __restrict__ Wt, const float* __restrict__ Wa,
                             const float* __restrict__ WxT, const float* __restrict__ Wb,
                             const float* __restrict__ Wg, const float* __restrict__ We,
                             const float* __restrict__ W1) {
    int stride = gridDim.x * blockDim.x;
    int t0 = blockIdx.x * blockDim.x + threadIdx.x;
    for (int i = t0; i < 2560 * 512; i += stride) {
        int n = i >> 9, k = i & 511;
        float w;
        if (n < 2048) {
            int g = (n >> 3) & 3, j = ((n >> 5) << 3) + (n & 7);
            w = Uh[(size_t)k * 2048 + g * 512 + j];
        } else {
            w = Wa[(size_t)k * 512 + (n - 2048)];
        }
        g_WTb[i] = __float2half(w);
    }
    for (int i = t0; i < 2560 * 64; i += stride) {
        int n = i >> 6, k = i & 63;
        float w;
        if (n < 2048) {
            int g = (n >> 3) & 3, j = ((n >> 5) << 3) + (n & 7);
            if (k < 63) w = Wx[(size_t)k * 2048 + g * 512 + j];
            else        w = (g < 3) ? Wt[g * 512 + j] : 0.f;
        } else {
            w = (k < 63) ? WxT[(size_t)k * 512 + (n - 2048)] : 0.f;
        }
        g_WPRE[i] = __float2half(w);
    }
    for (int i = t0; i < 1024 * 512; i += stride) {
        int n = i >> 9, k = i & 511;
        float w = (n < 512) ? Wb[(size_t)k * 512 + n] : Wg[(size_t)k * 512 + (n - 512)];
        g_WT2[i] = __float2half(w);
    }
    for (int i = t0; i < 512 * 512; i += stride) {
        int n = i >> 9, k = i & 511;
        g_WT3[i] = __float2half(We[(size_t)k * 512 + n]);
    }
    for (int i = t0; i < 256 * 512; i += stride) {
        int n = i >> 9, k = i & 511;
        g_WTh[i] = __float2half(W1[(size_t)k * 256 + n]);
    }
}

__global__ void prep_s(const float* __restrict__ init_proj) {
    int h = threadIdx.x;
    float s = 0.f;
    for (int f = 0; f < 64; ++f) s += init_proj[f * 512 + h];
    g_s[h] = s;
}

__global__ void prep_sA(const float* __restrict__ Wa) {
    int h = threadIdx.x;
    float acc = 0.f;
    for (int k = 0; k < 512; ++k) acc += g_s[k] * Wa[k * 512 + h];
    g_sA[h] = acc;
}

__global__ void prep_A(const float* __restrict__ inp) {
    int stride = gridDim.x * blockDim.x;
    int t0 = blockIdx.x * blockDim.x + threadIdx.x;
    for (int i = t0; i < 65536 * 64; i += stride) {
        int r = i >> 6, k = i & 63;
        float v = (k < 63) ? inp[(size_t)r * 64 + 1 + k] : inp[(size_t)r * 64];
        g_APRE[i] = __float2half(v);
    }
}

// ---------------- fp16 HMMA GEMM ----------------
// MODE 1: N=2048 Uh(perm) only: FUSED gates -> C, HcH(oh)
// MODE 2: N=1024 [Wb|Wg]: c<512 -> o2h=HBh(+e0); else oh=HGh
// MODE 3: N=512 We: h=tanh(acc + e0h + e1) -> oh (next Ah slot)
// MODE 4: N=256 W1: o0 = relu(acc+e0)
// MODE 5: N=2560 pre: c<2048 -> ZX16(perm); else TG16
// MODE 6: N=512 Wa (B = WTb+2048*512): o2h = MEMA slot (fp16)
template <int MODE>
__global__ __launch_bounds__(256, 2)
void mma_gemm(const __half* __restrict__ A, int lda, int K,
              const __half* __restrict__ Bh,
              const float* __restrict__ e0, const float* __restrict__ e1,
              const __half* __restrict__ e0h,
              float* __restrict__ o0,
              __half* __restrict__ o2h, __half* __restrict__ oh,
              const __half* __restrict__ zxp, const __half* __restrict__ tgp,
              float* __restrict__ Cp,
              const float* __restrict__ inp, const float* __restrict__ WtT,
              const float* __restrict__ bT) {
    extern __shared__ char smem[];
    uint32_t sb = smem_u32(smem);
    const int tid = threadIdx.x;
    const int lane = tid & 31, wid = tid >> 5;
    const int wm = wid & 1, wn = wid >> 1;
    const int gid = lane >> 2, tq = lane & 3;
    const int m0 = blockIdx.y * 128, n0 = blockIdx.x * 128;

    const int kch = K >> 6;

    float acc[4][4][4];
    #pragma unroll
    for (int a = 0; a < 4; ++a)
        #pragma unroll
        for (int b2 = 0; b2 < 4; ++b2)
            #pragma unroll
            for (int c = 0; c < 4; ++c) acc[a][b2][c] = 0.f;

    auto copy_chunk = [&](int ch, int s) {
        int kc = ch << 6;
        uint32_t base = sb + s * STAGE_BYTES;
        #pragma unroll
        for (int i = 0; i < 4; ++i) {
            int lin = tid + (i << 8);
            int r = lin >> 3;
            int c16 = (lin & 7) << 4;
            cp16(base + r * 144 + c16,
                 (const char*)(A + (size_t)(m0 + r) * lda + kc) + c16);
            cp16(base + 18432 + r * 144 + c16,
                 (const char*)(Bh + (size_t)(n0 + r) * K + kc) + c16);
        }
    };

    copy_chunk(0, 0);
    cp_commit();

    const int arow = wm * 64 + (lane & 15);
    const int acol = (lane >> 4) << 4;
    const int brow = wn * 32 + (lane & 7) + ((lane >> 4) << 3);
    const int bcol = ((lane >> 3) & 1) << 4;

    for (int ch = 0; ch < kch; ++ch) {
        if (ch + 1 < kch) {
            copy_chunk(ch + 1, (ch + 1) & 1);
            cp_commit();
            asm volatile("cp.async.wait_group 1;" ::: "memory");
        } else {
            asm volatile("cp.async.wait_group 0;" ::: "memory");
        }
        __syncthreads();

        uint32_t abase = sb + (ch & 1) * STAGE_BYTES;
        uint32_t bbase = abase + 18432;
        #pragma unroll
        for (int k16 = 0; k16 < 4; ++k16) {
            int kb = k16 << 5;
            uint32_t bf[2][4];
            #pragma unroll
            for (int ni2 = 0; ni2 < 2; ++ni2)
                ldm4(bf[ni2], bbase + (brow + ni2 * 16) * 144 + kb + bcol);
            uint32_t af[4][4];
            #pragma unroll
            for (int mi = 0; mi < 4; ++mi)
                ldm4(af[mi], abase + (arow + mi * 16) * 144 + kb + acol);
            #pragma unroll
            for (int ni2 = 0; ni2 < 2; ++ni2)
                #pragma unroll
                for (int mi = 0; mi < 4; ++mi) {
                    mma16816(acc[mi][ni2 * 2],     af[mi], bf[ni2][0], bf[ni2][1]);
                    mma16816(acc[mi][ni2 * 2 + 1], af[mi], bf[ni2][2], bf[ni2][3]);
                }
        }
        __syncthreads();
    }

    // ---- epilogues ----
    if (MODE == 1) {
        int blk = (n0 + wn * 32) >> 5;
        int j = blk * 8 + (tq << 1);
        #pragma unroll
        for (int mi = 0; mi < 4; ++mi) {
            int mb = m0 + wm * 64 + mi * 16 + gid;
            #pragma unroll
            for (int hf = 0; hf < 2; ++hf) {
                int r = mb + hf * 8;
                int ko = hf * 2;
                const __half* zxr = zxp + (size_t)r * 2048 + blk * 32 + (tq << 1);
                float2 xi = __half22float2(*(const __half2*)(zxr));
                float2 xf = __half22float2(*(const __half2*)(zxr + 8));
                float2 xo = __half22float2(*(const __half2*)(zxr + 16));
                float2 xc = __half22float2(*(const __half2*)(zxr + 24));
                float2 tg2 = __half22float2(*(const __half2*)(tgp + (size_t)r * 512 + j));
                float2 cold = *(float2*)(Cp + (size_t)r * 512 + j);
                float ch0 = tanh_app(acc[mi][3][ko] + xc.x);
                float ch1 = tanh_app(acc[mi][3][ko + 1] + xc.y);
                float c0 = fmaf(sigmf_(acc[mi][1][ko] + xf.x), cold.x,
                                (sigmf_(acc[mi][0][ko] + xi.x) + tg2.x) * ch0);
                float c1 = fmaf(sigmf_(acc[mi][1][ko + 1] + xf.y), cold.y,
                                (sigmf_(acc[mi][0][ko + 1] + xi.y) + tg2.y) * ch1);
                *(float2*)(Cp + (size_t)r * 512 + j) = make_float2(c0, c1);
                float h0 = sigmf_(acc[mi][2][ko] + xo.x) * tanh_app(c0);
                float h1 = sigmf_(acc[mi][2][ko + 1] + xo.y) * tanh_app(c1);
                *(__half2*)(oh + (size_t)r * 512 + j) = __floats2half2_rn(h0, h1);
            }
        }
        return;
    }

    auto epi = [&](int m, int c, float x, float y) {
        if (MODE == 2) {
            if (c < 512) {
                *(__half2*)(o2h + (size_t)m * 512 + c) =
                    __floats2half2_rn(x + e0[c], y + e0[c + 1]);
            } else {
                *(__half2*)(oh + (size_t)m * 512 + (c - 512)) = __floats2half2_rn(x, y);
            }
        } else if (MODE == 3) {
            float2 hg = __half22float2(*(const __half2*)(e0h + (size_t)m * 512 + c));
            float h0 = tanh_app(x + hg.x + e1[c]);
            float h1 = tanh_app(y + hg.y + e1[c + 1]);
            *(__half2*)(oh + (size_t)m * 512 + c) = __floats2half2_rn(h0, h1);
        } else if (MODE == 4) {
            *(float2*)(o0 + (size_t)m * 256 + c) =
                make_float2(fmaxf(x + e0[c], 0.f), fmaxf(y + e0[c + 1], 0.f));
        } else if (MODE == 6) {
            *(__half2*)(o2h + (size_t)m * 512 + c) = __floats2half2_rn(x, y);
        } else {  // MODE 5
            int b_ = m >> 4, t_ = m & 15;
            size_t zr = (size_t)t_ * Bn + b_;
            if (c < 2048) {
                int g = (c >> 3) & 3;
                int j0 = ((c >> 5) << 3) + (c & 7);
                *(__half2*)(g_ZX16 + zr * 2048 + c) =
                    __floats2half2_rn(x + e0[g * 512 + j0], y + e0[g * 512 + j0 + 1]);
            } else {
                int j = c - 2048;
                float tv = inp[(size_t)m * 64];
                float t0v = sigm(x + sigm(tv * WtT[j]) + bT[j]);
                float t1v = sigm(y + sigm(tv * WtT[j + 1]) + bT[j + 1]);
                *(__half2*)(g_TG16 + zr * 512 + j) = __floats2half2_rn(t0v, t1v);
            }
        }
    };

    #pragma unroll
    for (int mi = 0; mi < 4; ++mi) {
        #pragma unroll
        for (int ni = 0; ni < 4; ++ni) {
            float* cc = acc[mi][ni];
            int m = m0 + wm * 64 + mi * 16 + gid;
            int c = n0 + wn * 32 + ni * 8 + (tq << 1);
            epi(m, c, cc[0], cc[1]);
            epi(m + 8, c, cc[2], cc[3]);
        }
    }
}

// ---------------- t=0 gates ----------------
__global__ void gates0_k(const __half* __restrict__ ZX, const __half* __restrict__ TG,
                         float* __restrict__ C, __half* __restrict__ HcH) {
    int idx = blockIdx.x * blockDim.x + threadIdx.x;
    int b = idx >> 9, j = idx & 511;
    int blk = j >> 3, jr = j & 7;
    const __half* zx = ZX + (size_t)b * 2048 + blk * 32 + jr;
    float zi = __half2float(zx[0]);
    float zo = __half2float(zx[16]);
    float zc = __half2float(zx[24]);
    float tg = __half2float(TG[idx]);
    float ch = tanh_app(zc);
    float c = (sigmf_(zi) + tg) * ch;
    C[idx] = c;
    HcH[idx] = __float2half(sigmf_(zo) * tanh_app(c));
}

// ---------------- attention: vectorized __half2 path ----------------
__global__ void __launch_bounds__(256) attn_k(const __half* __restrict__ HB,
                                              const float* __restrict__ va,
                                              __half* __restrict__ CXH, int t) {
    int b = blockIdx.x, tid = threadIdx.x;
    __shared__ float sred[15][8];
    __shared__ float se[15];
    float2 hb = __half22float2(((const __half2*)(HB + (size_t)b * 512))[tid]);
    float2 va2 = *(const float2*)(va + 2 * tid);
    float2 sA2 = *(const float2*)(g_sA + 2 * tid);
    float2 s2  = *(const float2*)(g_s + 2 * tid);
    int lane = tid & 31, wp = tid >> 5;

    #pragma unroll
    for (int d = 0; d < 15; ++d) {
        int j = t - 15 + d;
        float m0, m1;
        if (j < 0) {
            m0 = sA2.x; m1 = sA2.y;
        } else {
            float2 f = __half22float2(
                ((const __half2*)(g_MEMA16 + (size_t)j * HSLOT + (size_t)b * 512))[tid]);
            m0 = f.x; m1 = f.y;
        }
        float s = va2.x * tanh_app(m0 + hb.x) + va2.y * tanh_app(m1 + hb.y);
        #pragma unroll
        for (int off = 16; off; off >>= 1) s += __shfl_xor_sync(0xffffffffu, s, off);
        if (lane == 0) sred[d][wp] = s;
    }
    __syncthreads();
    if (tid < 15) {
        float e = 0.f;
        #pragma unroll
        for (int w2 = 0; w2 < 8; ++w2) e += sred[tid][w2];
        se[tid] = e;
    }
    __syncthreads();

    float mx = -1e30f;
    #pragma unroll
    for (int d = 0; d < 15; ++d) mx = fmaxf(mx, se[d]);
    float al[15], sum = 0.f;
    #pragma unroll
    for (int d = 0; d < 15; ++d) { al[d] = __expf(se[d] - mx); sum += al[d]; }
    float inv = __fdividef(1.f, sum);
    float c0 = 0.f, c1 = 0.f;
    #pragma unroll
    for (int d = 0; d < 15; ++d) {
        int j = t - 15 + d;
        float a = al[d] * inv;
        float m0, m1;
        if (j < 0) {
            m0 = s2.x; m1 = s2.y;
        } else {
            float2 f = __half22float2(
                ((const __half2*)(g_Ah + (size_t)(j + 1) * HSLOT + (size_t)b * 512))[tid]);
            m0 = f.x; m1 = f.y;
        }
        c0 = fmaf(a, m0, c0);
        c1 = fmaf(a, m1, c1);
    }
    ((__half2*)(CXH + (size_t)b * 512))[tid] = __floats2half2_rn(c0, c1);
}

// ---------------- head layers 2,3 ----------------
__global__ void head2_k(const float* __restrict__ HD1, const float* __restrict__ W2,
                        const float* __restrict__ b2, float* __restrict__ HD2) {
    int warp = (blockIdx.x * blockDim.x + threadIdx.x) >> 5;
    int lane = threadIdx.x & 31;
    if (warp >= Bn) return;
    const float* h = HD1 + (size_t)warp * 256;
    float acc = 0.f;
    for (int k = 0; k < 256; ++k) acc = fmaf(h[k], W2[k * 32 + lane], acc);
    HD2[(size_t)warp * 32 + lane] = fmaxf(acc + b2[lane], 0.f);
}

__global__ void head3_k(const float* __restrict__ HD2, const float* __restrict__ W3,
                        const float* __restrict__ b3, float* __restrict__ out) {
    int b = blockIdx.x * blockDim.x + threadIdx.x;
    if (b >= Bn) return;
    float a0 = b3[0], a1 = b3[1];
    const float* h = HD2 + (size_t)b * 32;
    #pragma unroll
    for (int k = 0; k < 32; ++k) {
        float hv = h[k];
        a0 = fmaf(hv, W3[k * 2 + 0], a0);
        a1 = fmaf(hv, W3[k * 2 + 1], a1);
    }
    float m = fmaxf(a0, a1);
    float e0v = expf(a0 - m), e1v = expf(a1 - m);
    float inv = 1.f / (e0v + e1v);
    out[(size_t)b * 2 + 0] = e0v * inv;
    out[(size_t)b * 2 + 1] = e1v * inv;
}

// ---------------- launcher ----------------
extern "C" void kernel_launch(void* const* d_in, const int* in_sizes, int n_in,
                              void* d_out, int out_size) {
    const float* inputs    = (const float*)d_in[0];
    const float* init_proj = (const float*)d_in[1];
    const float* Wx  = (const float*)d_in[3];
    const float* Uh  = (const float*)d_in[4];
    const float* Wt  = (const float*)d_in[5];
    const float* b   = (const float*)d_in[6];
    const float* WxT = (const float*)d_in[7];
    const float* WtT = (const float*)d_in[8];
    const float* bT  = (const float*)d_in[9];
    const float* Wa  = (const float*)d_in[10];
    const float* Wb  = (const float*)d_in[11];
    const float* va  = (const float*)d_in[12];
    const float* ba  = (const float*)d_in[13];
    const float* We  = (const float*)d_in[14];
    const float* Wg  = (const float*)d_in[15];
    const float* bh  = (const float*)d_in[16];
    const float* W1  = (const float*)d_in[17];
    const float* b1  = (const float*)d_in[18];
    const float* W2  = (const float*)d_in[19];
    const float* b2  = (const float*)d_in[20];
    const float* W3  = (const float*)d_in[21];
    const float* b3  = (const float*)d_in[22];
    float* out = (float*)d_out;

    static cudaStream_t s2 = nullptr;
    static cudaEvent_t evF[16], evJ[16];
    if (!s2) {
        cudaStreamCreateWithFlags(&s2, cudaStreamNonBlocking);
        for (int i = 0; i < 16; ++i) {
            cudaEventCreateWithFlags(&evF[i], cudaEventDisableTiming);
            cudaEventCreateWithFlags(&evJ[i], cudaEventDisableTiming);
        }
        cudaFuncSetAttribute(mma_gemm<1>, cudaFuncAttributeMaxDynamicSharedMemorySize, SMEM_BYTES);
        cudaFuncSetAttribute(mma_gemm<2>, cudaFuncAttributeMaxDynamicSharedMemorySize, SMEM_BYTES);
        cudaFuncSetAttribute(mma_gemm<3>, cudaFuncAttributeMaxDynamicSharedMemorySize, SMEM_BYTES);
        cudaFuncSetAttribute(mma_gemm<4>, cudaFuncAttributeMaxDynamicSharedMemorySize, SMEM_BYTES);
        cudaFuncSetAttribute(mma_gemm<5>, cudaFuncAttributeMaxDynamicSharedMemorySize, SMEM_BYTES);
        cudaFuncSetAttribute(mma_gemm<6>, cudaFuncAttributeMaxDynamicSharedMemorySize, SMEM_BYTES);
    }

    __half *Ah, *APRE, *WTb, *WPRE, *WT2, *WT3, *WTh, *MEMA16, *ZX16, *TG16, *HcH, *HBh, *HGh, *CXH;
    float *C, *HD1, *HD2;
    cudaGetSymbolAddress((void**)&Ah, g_Ah);
    cudaGetSymbolAddress((void**)&APRE, g_APRE);
    cudaGetSymbolAddress((void**)&WTb, g_WTb);
    cudaGetSymbolAddress((void**)&WPRE, g_WPRE);
    cudaGetSymbolAddress((void**)&WT2, g_WT2);
    cudaGetSymbolAddress((void**)&WT3, g_WT3);
    cudaGetSymbolAddress((void**)&WTh, g_WTh);
    cudaGetSymbolAddress((void**)&MEMA16, g_MEMA16);
    cudaGetSymbolAddress((void**)&ZX16, g_ZX16);
    cudaGetSymbolAddress((void**)&TG16, g_TG16);
    cudaGetSymbolAddress((void**)&HcH, g_HcH);
    cudaGetSymbolAddress((void**)&HBh, g_HBh);
    cudaGetSymbolAddress((void**)&HGh, g_HGh);
    cudaGetSymbolAddress((void**)&CXH, g_CXH);
    cudaGetSymbolAddress((void**)&C, g_C);
    cudaGetSymbolAddress((void**)&HD1, g_HD1);
    cudaGetSymbolAddress((void**)&HD2, g_HD2);

    prep_weights<<<1024, 256>>>(Uh, Wx, Wt, Wa, WxT, Wb, Wg, We, W1);
    prep_s<<<1, 512>>>(init_proj);
    prep_sA<<<1, 512>>>(Wa);
    prep_A<<<2048, 256>>>(inputs);

    // pre-GEMM: ZX(perm) + TG for all steps
    mma_gemm<5><<<dim3(20, 512), 256, SMEM_BYTES>>>(
        APRE, 64, 64, WPRE,
        b, nullptr, nullptr, nullptr, nullptr, nullptr,
        nullptr, nullptr, nullptr, inputs, WtT, bT);

    for (int t = 0; t < 16; ++t) {
        if (t > 0) {
            // fork: Wa-part (MEMA slot t-1) on stream s2, overlapping Uh-part + MODE2
            cudaEventRecord(evF[t], 0);
            cudaStreamWaitEvent(s2, evF[t], 0);
            mma_gemm<6><<<dim3(4, 32), 256, SMEM_BYTES, s2>>>(
                Ah + (size_t)t * HSLOT, 512, 512, WTb + (size_t)2048 * 512,
                nullptr, nullptr, nullptr, nullptr,
                MEMA16 + (size_t)(t - 1) * HSLOT, nullptr,
                nullptr, nullptr, nullptr, nullptr, nullptr, nullptr);
            cudaEventRecord(evJ[t], s2);
            // Uh-part with fused gates on main stream
            mma_gemm<1><<<dim3(16, 32), 256, SMEM_BYTES>>>(
                Ah + (size_t)t * HSLOT, 512, 512, WTb,
                nullptr, nullptr, nullptr, nullptr,
                nullptr, HcH,
                ZX16 + (size_t)t * Bn * 2048, TG16 + (size_t)t * Bn * 512, C,
                nullptr, nullptr, nullptr);
        } else {
            gates0_k<<<8192, 256>>>(ZX16, TG16, C, HcH);
        }
        mma_gemm<2><<<dim3(8, 32), 256, SMEM_BYTES>>>(
            HcH, 512, 512, WT2,
            ba, nullptr, nullptr, nullptr,
            HBh, HGh,
            nullptr, nullptr, nullptr, nullptr, nullptr, nullptr);
        if (t > 0) cudaStreamWaitEvent(0, evJ[t], 0);   // join before attention
        attn_k<<<4096, 256>>>(HBh, va, CXH, t);
        mma_gemm<3><<<dim3(4, 32), 256, SMEM_BYTES>>>(
            CXH, 512, 512, WT3,
            nullptr, bh, HGh, nullptr,
            nullptr, Ah + (size_t)(t + 1) * HSLOT,
            nullptr, nullptr, nullptr, nullptr, nullptr, nullptr);
    }

    mma_gemm<4><<<dim3(2, 32), 256, SMEM_BYTES>>>(
        Ah + (size_t)16 * HSLOT, 512, 512, WTh,
        b1, nullptr, nullptr, HD1,
        nullptr, nullptr,
        nullptr, nullptr, nullptr, nullptr, nullptr, nullptr);
    head2_k<<<512, 256>>>(HD1, W2, b2, HD2);
    head3_k<<<16, 256>>>(HD2, W3, b3, out);
}

// round 13
// speedup vs baseline: 1.3304x; 1.0146x over previous
#include <cuda_runtime.h>
#include <cuda_fp16.h>
#include <math.h>
#include <stdint.h>

#define Bn 4096
#define HSLOT ((size_t)Bn * 512)
#define STAGE_BYTES 36864
#define SMEM_BYTES (2 * STAGE_BYTES)

// Gate permutation: physical col p (p<2048) <-> logical (gate g, unit j):
//   g = (p>>3)&3, j = ((p>>5)<<3) + (p&7)

// ---------------- device scratch ----------------
__device__ __half g_Ah[(size_t)17 * HSLOT];         // slot j+1 holds h_j (fp16); slot 0 unused
__device__ __half g_APRE[(size_t)65536 * 64];
__device__ __half g_WTb[(size_t)3072 * 512];        // [Uh(perm,2048) | Wa(512) | We(512)], n-major
__device__ __half g_WPRE[(size_t)2560 * 64];
__device__ __half g_WT2[1024 * 512];                // [Wb | Wg]
__device__ __half g_WTh[256 * 512];                 // W1
__device__ __half g_ZX16[(size_t)16 * Bn * 2048];
__device__ __half g_TG16[(size_t)16 * Bn * 512];
__device__ __half g_MEMA16[(size_t)15 * HSLOT];     // slot j: h_j @ Wa
__device__ __half g_HWE16[(size_t)15 * HSLOT];      // slot j: h_j @ We
__device__ __half g_HcH[(size_t)Bn * 512];
__device__ __half g_HBh[(size_t)Bn * 512];
__device__ __half g_HGh[(size_t)Bn * 512];
__device__ float g_C[(size_t)Bn * 512];
__device__ float g_HD1[(size_t)Bn * 256];
__device__ float g_HD2[(size_t)Bn * 32];
__device__ float g_s[512];
__device__ float g_sA[512];
__device__ float g_sWe[512];

__device__ __forceinline__ float sigm(float x) { return 1.f / (1.f + expf(-x)); }
__device__ __forceinline__ float sigmf_(float x) { return __fdividef(1.f, 1.f + __expf(-x)); }
__device__ __forceinline__ float tanh_app(float x) {
    float y; asm("tanh.approx.f32 %0, %1;" : "=f"(y) : "f"(x)); return y;
}

__device__ __forceinline__ uint32_t smem_u32(const void* p) {
    uint32_t a;
    asm("{ .reg .u64 t; cvta.to.shared.u64 t, %1; cvt.u32.u64 %0, t; }" : "=r"(a) : "l"(p));
    return a;
}
__device__ __forceinline__ void ldm4(uint32_t* r, uint32_t a) {
    asm volatile("ldmatrix.sync.aligned.m8n8.x4.shared.b16 {%0,%1,%2,%3}, [%4];"
                 : "=r"(r[0]), "=r"(r[1]), "=r"(r[2]), "=r"(r[3]) : "r"(a));
}
__device__ __forceinline__ void mma16816(float* c, const uint32_t* a, uint32_t b0, uint32_t b1) {
    asm volatile("mma.sync.aligned.m16n8k16.row.col.f32.f16.f16.f32 "
                 "{%0,%1,%2,%3}, {%4,%5,%6,%7}, {%8,%9}, {%0,%1,%2,%3};"
                 : "+f"(c[0]), "+f"(c[1]), "+f"(c[2]), "+f"(c[3])
                 : "r"(a[0]), "r"(a[1]), "r"(a[2]), "r"(a[3]), "r"(b0), "r"(b1));
}
__device__ __forceinline__ void cp16(uint32_t saddr, const void* gptr) {
    asm volatile("cp.async.cg.shared.global [%0], [%1], 16;"
                 :: "r"(saddr), "l"(__cvta_generic_to_global(gptr)) : "memory");
}
__device__ __forceinline__ void cp_commit() {
    asm volatile("cp.async.commit_group;" ::: "memory");
}

// ---------------- prep kernels ----------------
__global__ void prep_weights(const float* __restrict__ Uh, const float* __restrict__ Wx,
                             const float* __restrict__ Wt, const float* __restrict__ Wa,
                             const float* __restrict__ WxT, const float* __restrict__ Wb,
                             const float* __restrict__ Wg, const float* __restrict__ We,
                             const float* __restrict__ W1) {
    int stride = gridDim.x * blockDim.x;
    int t0 = blockIdx.x * blockDim.x + threadIdx.x;
    for (int i = t0; i < 3072 * 512; i += stride) {
        int n = i >> 9, k = i & 511;
        float w;
        if (n < 2048) {
            int g = (n >> 3) & 3, j = ((n >> 5) << 3) + (n & 7);
            w = Uh[(size_t)k * 2048 + g * 512 + j];
        } else if (n < 2560) {
            w = Wa[(size_t)k * 512 + (n - 2048)];
        } else {
            w = We[(size_t)k * 512 + (n - 2560)];
        }
        g_WTb[i] = __float2half(w);
    }
    for (int i = t0; i < 2560 * 64; i += stride) {
        int n = i >> 6, k = i & 63;
        float w;
        if (n < 2048) {
            int g = (n >> 3) & 3, j = ((n >> 5) << 3) + (n & 7);
            if (k < 63) w = Wx[(size_t)k * 2048 + g * 512 + j];
            else        w = (g < 3) ? Wt[g * 512 + j] : 0.f;
        } else {
            w = (k < 63) ? WxT[(size_t)k * 512 + (n - 2048)] : 0.f;
        }
        g_WPRE[i] = __float2half(w);
    }
    for (int i = t0; i < 1024 * 512; i += stride) {
        int n = i >> 9, k = i & 511;
        float w = (n < 512) ? Wb[(size_t)k * 512 + n] : Wg[(size_t)k * 512 + (n - 512)];
        g_WT2[i] = __float2half(w);
    }
    for (int i = t0; i < 256 * 512; i += stride) {
        int n = i >> 9, k = i & 511;
        g_WTh[i] = __float2half(W1[(size_t)k * 256 + n]);
    }
}

__global__ void prep_s(const float* __restrict__ init_proj) {
    int h = threadIdx.x;
    float s = 0.f;
    for (int f = 0; f < 64; ++f) s += init_proj[f * 512 + h];
    g_s[h] = s;
}

__global__ void prep_sA(const float* __restrict__ Wa, const float* __restrict__ We) {
    int h = threadIdx.x;
    float a = 0.f, e = 0.f;
    for (int k = 0; k < 512; ++k) {
        float sv = g_s[k];
        a = fmaf(sv, Wa[k * 512 + h], a);
        e = fmaf(sv, We[k * 512 + h], e);
    }
    g_sA[h] = a;
    g_sWe[h] = e;
}

__global__ void prep_A(const float* __restrict__ inp) {
    int stride = gridDim.x * blockDim.x;
    int t0 = blockIdx.x * blockDim.x + threadIdx.x;
    for (int i = t0; i < 65536 * 64; i += stride) {
        int r = i >> 6, k = i & 63;
        float v = (k < 63) ? inp[(size_t)r * 64 + 1 + k] : inp[(size_t)r * 64];
        g_APRE[i] = __float2half(v);
    }
}

// ---------------- fp16 HMMA GEMM ----------------
// MODE 1: N=3072 [Uh(perm)|Wa|We]: n<2048 -> FUSED gates -> C, HcH(oh);
//         2048..2559 -> o2h (MEMA slot); 2560..3071 -> o3h (HWE slot)
// MODE 2: N=1024 [Wb|Wg]: c<512 -> o2h=HBh(+e0); else oh=HGh
// MODE 4: N=256 W1: o0 = relu(acc+e0)
// MODE 5: N=2560 pre: c<2048 -> ZX16(perm); else TG16
template <int MODE>
__global__ __launch_bounds__(256, 2)
void mma_gemm(const __half* __restrict__ A, int lda, int K,
              const __half* __restrict__ Bh,
              const float* __restrict__ e0,
              float* __restrict__ o0,
              __half* __restrict__ o2h, __half* __restrict__ o3h,
              __half* __restrict__ oh,
              const __half* __restrict__ zxp, const __half* __restrict__ tgp,
              float* __restrict__ Cp,
              const float* __restrict__ inp, const float* __restrict__ WtT,
              const float* __restrict__ bT) {
    extern __shared__ char smem[];
    uint32_t sb = smem_u32(smem);
    const int tid = threadIdx.x;
    const int lane = tid & 31, wid = tid >> 5;
    const int wm = wid & 1, wn = wid >> 1;
    const int gid = lane >> 2, tq = lane & 3;
    const int m0 = blockIdx.y * 128, n0 = blockIdx.x * 128;

    const int kch = K >> 6;

    float acc[4][4][4];
    #pragma unroll
    for (int a = 0; a < 4; ++a)
        #pragma unroll
        for (int b2 = 0; b2 < 4; ++b2)
            #pragma unroll
            for (int c = 0; c < 4; ++c) acc[a][b2][c] = 0.f;

    auto copy_chunk = [&](int ch, int s) {
        int kc = ch << 6;
        uint32_t base = sb + s * STAGE_BYTES;
        #pragma unroll
        for (int i = 0; i < 4; ++i) {
            int lin = tid + (i << 8);
            int r = lin >> 3;
            int c16 = (lin & 7) << 4;
            cp16(base + r * 144 + c16,
                 (const char*)(A + (size_t)(m0 + r) * lda + kc) + c16);
            cp16(base + 18432 + r * 144 + c16,
                 (const char*)(Bh + (size_t)(n0 + r) * K + kc) + c16);
        }
    };

    copy_chunk(0, 0);
    cp_commit();

    const int arow = wm * 64 + (lane & 15);
    const int acol = (lane >> 4) << 4;
    const int brow = wn * 32 + (lane & 7) + ((lane >> 4) << 3);
    const int bcol = ((lane >> 3) & 1) << 4;

    for (int ch = 0; ch < kch; ++ch) {
        if (ch + 1 < kch) {
            copy_chunk(ch + 1, (ch + 1) & 1);
            cp_commit();
            asm volatile("cp.async.wait_group 1;" ::: "memory");
        } else {
            asm volatile("cp.async.wait_group 0;" ::: "memory");
        }
        __syncthreads();

        uint32_t abase = sb + (ch & 1) * STAGE_BYTES;
        uint32_t bbase = abase + 18432;
        #pragma unroll
        for (int k16 = 0; k16 < 4; ++k16) {
            int kb = k16 << 5;
            uint32_t bf[2][4];
            #pragma unroll
            for (int ni2 = 0; ni2 < 2; ++ni2)
                ldm4(bf[ni2], bbase + (brow + ni2 * 16) * 144 + kb + bcol);
            uint32_t af[4][4];
            #pragma unroll
            for (int mi = 0; mi < 4; ++mi)
                ldm4(af[mi], abase + (arow + mi * 16) * 144 + kb + acol);
            #pragma unroll
            for (int ni2 = 0; ni2 < 2; ++ni2)
                #pragma unroll
                for (int mi = 0; mi < 4; ++mi) {
                    mma16816(acc[mi][ni2 * 2],     af[mi], bf[ni2][0], bf[ni2][1]);
                    mma16816(acc[mi][ni2 * 2 + 1], af[mi], bf[ni2][2], bf[ni2][3]);
                }
        }
        __syncthreads();
    }

    // ---- epilogues ----
    if (MODE == 1) {
        if (n0 < 2048) {
            int blk = (n0 + wn * 32) >> 5;
            int j = blk * 8 + (tq << 1);
            #pragma unroll
            for (int mi = 0; mi < 4; ++mi) {
                int mb = m0 + wm * 64 + mi * 16 + gid;
                #pragma unroll
                for (int hf = 0; hf < 2; ++hf) {
                    int r = mb + hf * 8;
                    int ko = hf * 2;
                    const __half* zxr = zxp + (size_t)r * 2048 + blk * 32 + (tq << 1);
                    float2 xi = __half22float2(*(const __half2*)(zxr));
                    float2 xf = __half22float2(*(const __half2*)(zxr + 8));
                    float2 xo = __half22float2(*(const __half2*)(zxr + 16));
                    float2 xc = __half22float2(*(const __half2*)(zxr + 24));
                    float2 tg2 = __half22float2(*(const __half2*)(tgp + (size_t)r * 512 + j));
                    float2 cold = *(float2*)(Cp + (size_t)r * 512 + j);
                    float ch0 = tanh_app(acc[mi][3][ko] + xc.x);
                    float ch1 = tanh_app(acc[mi][3][ko + 1] + xc.y);
                    float c0 = fmaf(sigmf_(acc[mi][1][ko] + xf.x), cold.x,
                                    (sigmf_(acc[mi][0][ko] + xi.x) + tg2.x) * ch0);
                    float c1 = fmaf(sigmf_(acc[mi][1][ko + 1] + xf.y), cold.y,
                                    (sigmf_(acc[mi][0][ko + 1] + xi.y) + tg2.y) * ch1);
                    *(float2*)(Cp + (size_t)r * 512 + j) = make_float2(c0, c1);
                    float h0 = sigmf_(acc[mi][2][ko] + xo.x) * tanh_app(c0);
                    float h1 = sigmf_(acc[mi][2][ko + 1] + xo.y) * tanh_app(c1);
                    *(__half2*)(oh + (size_t)r * 512 + j) = __floats2half2_rn(h0, h1);
                }
            }
        } else {
            __half* dst = (n0 < 2560) ? o2h : o3h;
            int base = (n0 < 2560) ? 2048 : 2560;
            #pragma unroll
            for (int mi = 0; mi < 4; ++mi)
                #pragma unroll
                for (int ni = 0; ni < 4; ++ni) {
                    float* cc = acc[mi][ni];
                    int m = m0 + wm * 64 + mi * 16 + gid;
                    int c = n0 + wn * 32 + ni * 8 + (tq << 1) - base;
                    *(__half2*)(dst + (size_t)m * 512 + c) = __floats2half2_rn(cc[0], cc[1]);
                    *(__half2*)(dst + (size_t)(m + 8) * 512 + c) = __floats2half2_rn(cc[2], cc[3]);
                }
        }
        return;
    }

    auto epi = [&](int m, int c, float x, float y) {
        if (MODE == 2) {
            if (c < 512) {
                *(__half2*)(o2h + (size_t)m * 512 + c) =
                    __floats2half2_rn(x + e0[c], y + e0[c + 1]);
            } else {
                *(__half2*)(oh + (size_t)m * 512 + (c - 512)) = __floats2half2_rn(x, y);
            }
        } else if (MODE == 4) {
            *(float2*)(o0 + (size_t)m * 256 + c) =
                make_float2(fmaxf(x + e0[c], 0.f), fmaxf(y + e0[c + 1], 0.f));
        } else {  // MODE 5
            int b_ = m >> 4, t_ = m & 15;
            size_t zr = (size_t)t_ * Bn + b_;
            if (c < 2048) {
                int g = (c >> 3) & 3;
                int j0 = ((c >> 5) << 3) + (c & 7);
                *(__half2*)(g_ZX16 + zr * 2048 + c) =
                    __floats2half2_rn(x + e0[g * 512 + j0], y + e0[g * 512 + j0 + 1]);
            } else {
                int j = c - 2048;
                float tv = inp[(size_t)m * 64];
                float t0v = sigm(x + sigm(tv * WtT[j]) + bT[j]);
                float t1v = sigm(y + sigm(tv * WtT[j + 1]) + bT[j + 1]);
                *(__half2*)(g_TG16 + zr * 512 + j) = __floats2half2_rn(t0v, t1v);
            }
        }
    };

    #pragma unroll
    for (int mi = 0; mi < 4; ++mi) {
        #pragma unroll
        for (int ni = 0; ni < 4; ++ni) {
            float* cc = acc[mi][ni];
            int m = m0 + wm * 64 + mi * 16 + gid;
            int c = n0 + wn * 32 + ni * 8 + (tq << 1);
            epi(m, c, cc[0], cc[1]);
            epi(m + 8, c, cc[2], cc[3]);
        }
    }
}

// ---------------- t=0 gates ----------------
__global__ void gates0_k(const __half* __restrict__ ZX, const __half* __restrict__ TG,
                         float* __restrict__ C, __half* __restrict__ HcH) {
    int idx = blockIdx.x * blockDim.x + threadIdx.x;
    int b = idx >> 9, j = idx & 511;
    int blk = j >> 3, jr = j & 7;
    const __half* zx = ZX + (size_t)b * 2048 + blk * 32 + jr;
    float zi = __half2float(zx[0]);
    float zo = __half2float(zx[16]);
    float zc = __half2float(zx[24]);
    float tg = __half2float(TG[idx]);
    float ch = tanh_app(zc);
    float c = (sigmf_(zi) + tg) * ch;
    C[idx] = c;
    HcH[idx] = __float2half(sigmf_(zo) * tanh_app(c));
}

// ---------------- attention + h_new epilogue (MODE3 folded in via linearity) ----------------
// scores from MEMA16/sA as before; context formed from HWE16/sWe; h_new written to AhNext.
__global__ void __launch_bounds__(256) attn_k(const __half* __restrict__ HB,
                                              const __half* __restrict__ HG,
                                              const float* __restrict__ va,
                                              const float* __restrict__ bhv,
                                              __half* __restrict__ AhNext, int t) {
    int b = blockIdx.x, tid = threadIdx.x;
    __shared__ float sred[15][8];
    __shared__ float se[15];
    float2 hb = __half22float2(((const __half2*)(HB + (size_t)b * 512))[tid]);
    float2 va2 = *(const float2*)(va + 2 * tid);
    float2 sA2 = *(const float2*)(g_sA + 2 * tid);
    float2 sW2 = *(const float2*)(g_sWe + 2 * tid);
    int lane = tid & 31, wp = tid >> 5;

    #pragma unroll
    for (int d = 0; d < 15; ++d) {
        int j = t - 15 + d;
        float m0, m1;
        if (j < 0) {
            m0 = sA2.x; m1 = sA2.y;
        } else {
            float2 f = __half22float2(
                ((const __half2*)(g_MEMA16 + (size_t)j * HSLOT + (size_t)b * 512))[tid]);
            m0 = f.x; m1 = f.y;
        }
        float s = va2.x * tanh_app(m0 + hb.x) + va2.y * tanh_app(m1 + hb.y);
        #pragma unroll
        for (int off = 16; off; off >>= 1) s += __shfl_xor_sync(0xffffffffu, s, off);
        if (lane == 0) sred[d][wp] = s;
    }
    __syncthreads();
    if (tid < 15) {
        float e = 0.f;
        #pragma unroll
        for (int w2 = 0; w2 < 8; ++w2) e += sred[tid][w2];
        se[tid] = e;
    }
    __syncthreads();

    float mx = -1e30f;
    #pragma unroll
    for (int d = 0; d < 15; ++d) mx = fmaxf(mx, se[d]);
    float al[15], sum = 0.f;
    #pragma unroll
    for (int d = 0; d < 15; ++d) { al[d] = __expf(se[d] - mx); sum += al[d]; }
    float inv = __fdividef(1.f, sum);
    float c0 = 0.f, c1 = 0.f;
    #pragma unroll
    for (int d = 0; d < 15; ++d) {
        int j = t - 15 + d;
        float a = al[d] * inv;
        float m0, m1;
        if (j < 0) {
            m0 = sW2.x; m1 = sW2.y;
        } else {
            float2 f = __half22float2(
                ((const __half2*)(g_HWE16 + (size_t)j * HSLOT + (size_t)b * 512))[tid]);
            m0 = f.x; m1 = f.y;
        }
        c0 = fmaf(a, m0, c0);
        c1 = fmaf(a, m1, c1);
    }
    float2 hg = __half22float2(((const __half2*)(HG + (size_t)b * 512))[tid]);
    float2 bh2 = *(const float2*)(bhv + 2 * tid);
    float h0 = tanh_app(c0 + hg.x + bh2.x);
    float h1 = tanh_app(c1 + hg.y + bh2.y);
    ((__half2*)(AhNext + (size_t)b * 512))[tid] = __floats2half2_rn(h0, h1);
}

// ---------------- head layers 2,3 ----------------
__global__ void head2_k(const float* __restrict__ HD1, const float* __restrict__ W2,
                        const float* __restrict__ b2, float* __restrict__ HD2) {
    int warp = (blockIdx.x * blockDim.x + threadIdx.x) >> 5;
    int lane = threadIdx.x & 31;
    if (warp >= Bn) return;
    const float* h = HD1 + (size_t)warp * 256;
    float acc = 0.f;
    for (int k = 0; k < 256; ++k) acc = fmaf(h[k], W2[k * 32 + lane], acc);
    HD2[(size_t)warp * 32 + lane] = fmaxf(acc + b2[lane], 0.f);
}

__global__ void head3_k(const float* __restrict__ HD2, const float* __restrict__ W3,
                        const float* __restrict__ b3, float* __restrict__ out) {
    int b = blockIdx.x * blockDim.x + threadIdx.x;
    if (b >= Bn) return;
    float a0 = b3[0], a1 = b3[1];
    const float* h = HD2 + (size_t)b * 32;
    #pragma unroll
    for (int k = 0; k < 32; ++k) {
        float hv = h[k];
        a0 = fmaf(hv, W3[k * 2 + 0], a0);
        a1 = fmaf(hv, W3[k * 2 + 1], a1);
    }
    float m = fmaxf(a0, a1);
    float e0v = expf(a0 - m), e1v = expf(a1 - m);
    float inv = 1.f / (e0v + e1v);
    out[(size_t)b * 2 + 0] = e0v * inv;
    out[(size_t)b * 2 + 1] = e1v * inv;
}

// ---------------- launcher ----------------
extern "C" void kernel_launch(void* const* d_in, const int* in_sizes, int n_in,
                              void* d_out, int out_size) {
    const float* inputs    = (const float*)d_in[0];
    const float* init_proj = (const float*)d_in[1];
    const float* Wx  = (const float*)d_in[3];
    const float* Uh  = (const float*)d_in[4];
    const float* Wt  = (const float*)d_in[5];
    const float* b   = (const float*)d_in[6];
    const float* WxT = (const float*)d_in[7];
    const float* WtT = (const float*)d_in[8];
    const float* bT  = (const float*)d_in[9];
    const float* Wa  = (const float*)d_in[10];
    const float* Wb  = (const float*)d_in[11];
    const float* va  = (const float*)d_in[12];
    const float* ba  = (const float*)d_in[13];
    const float* We  = (const float*)d_in[14];
    const float* Wg  = (const float*)d_in[15];
    const float* bh  = (const float*)d_in[16];
    const float* W1  = (const float*)d_in[17];
    const float* b1  = (const float*)d_in[18];
    const float* W2  = (const float*)d_in[19];
    const float* b2  = (const float*)d_in[20];
    const float* W3  = (const float*)d_in[21];
    const float* b3  = (const float*)d_in[22];
    float* out = (float*)d_out;

    cudaFuncSetAttribute(mma_gemm<1>, cudaFuncAttributeMaxDynamicSharedMemorySize, SMEM_BYTES);
    cudaFuncSetAttribute(mma_gemm<2>, cudaFuncAttributeMaxDynamicSharedMemorySize, SMEM_BYTES);
    cudaFuncSetAttribute(mma_gemm<4>, cudaFuncAttributeMaxDynamicSharedMemorySize, SMEM_BYTES);
    cudaFuncSetAttribute(mma_gemm<5>, cudaFuncAttributeMaxDynamicSharedMemorySize, SMEM_BYTES);

    __half *Ah, *APRE, *WTb, *WPRE, *WT2, *WTh, *MEMA16, *HWE16, *ZX16, *TG16, *HcH, *HBh, *HGh;
    float *C, *HD1, *HD2;
    cudaGetSymbolAddress((void**)&Ah, g_Ah);
    cudaGetSymbolAddress((void**)&APRE, g_APRE);
    cudaGetSymbolAddress((void**)&WTb, g_WTb);
    cudaGetSymbolAddress((void**)&WPRE, g_WPRE);
    cudaGetSymbolAddress((void**)&WT2, g_WT2);
    cudaGetSymbolAddress((void**)&WTh, g_WTh);
    cudaGetSymbolAddress((void**)&MEMA16, g_MEMA16);
    cudaGetSymbolAddress((void**)&HWE16, g_HWE16);
    cudaGetSymbolAddress((void**)&ZX16, g_ZX16);
    cudaGetSymbolAddress((void**)&TG16, g_TG16);
    cudaGetSymbolAddress((void**)&HcH, g_HcH);
    cudaGetSymbolAddress((void**)&HBh, g_HBh);
    cudaGetSymbolAddress((void**)&HGh, g_HGh);
    cudaGetSymbolAddress((void**)&C, g_C);
    cudaGetSymbolAddress((void**)&HD1, g_HD1);
    cudaGetSymbolAddress((void**)&HD2, g_HD2);

    prep_weights<<<1024, 256>>>(Uh, Wx, Wt, Wa, WxT, Wb, Wg, We, W1);
    prep_s<<<1, 512>>>(init_proj);
    prep_sA<<<1, 512>>>(Wa, We);
    prep_A<<<2048, 256>>>(inputs);

    // pre-GEMM: ZX(perm) + TG for all steps
    mma_gemm<5><<<dim3(20, 512), 256, SMEM_BYTES>>>(
        APRE, 64, 64, WPRE,
        /*e0*/ b, /*o0*/ nullptr, /*o2h*/ nullptr, /*o3h*/ nullptr, /*oh*/ nullptr,
        /*zxp*/ nullptr, /*tgp*/ nullptr, /*Cp*/ nullptr,
        /*inp*/ inputs, /*WtT*/ WtT, /*bT*/ bT);

    for (int t = 0; t < 16; ++t) {
        if (t > 0) {
            // h_{t-1} @ [Uh|Wa|We] + fused gates -> HcH, C, MEMA/HWE slot t-1
            mma_gemm<1><<<dim3(24, 32), 256, SMEM_BYTES>>>(
                Ah + (size_t)t * HSLOT, 512, 512, WTb,
                /*e0*/ nullptr, /*o0*/ nullptr,
                /*o2h*/ MEMA16 + (size_t)(t - 1) * HSLOT,
                /*o3h*/ HWE16 + (size_t)(t - 1) * HSLOT,
                /*oh*/ HcH,
                /*zxp*/ ZX16 + (size_t)t * Bn * 2048, /*tgp*/ TG16 + (size_t)t * Bn * 512,
                /*Cp*/ C,
                /*inp*/ nullptr, /*WtT*/ nullptr, /*bT*/ nullptr);
        } else {
            gates0_k<<<8192, 256>>>(ZX16, TG16, C, HcH);
        }
        mma_gemm<2><<<dim3(8, 32), 256, SMEM_BYTES>>>(
            HcH, 512, 512, WT2,
            /*e0*/ ba, /*o0*/ nullptr, /*o2h*/ HBh, /*o3h*/ nullptr, /*oh*/ HGh,
            /*zxp*/ nullptr, /*tgp*/ nullptr, /*Cp*/ nullptr,
            /*inp*/ nullptr, /*WtT*/ nullptr, /*bT*/ nullptr);
        attn_k<<<4096, 256>>>(HBh, HGh, va, bh, Ah + (size_t)(t + 1) * HSLOT, t);
    }

    mma_gemm<4><<<dim3(2, 32), 256, SMEM_BYTES>>>(
        Ah + (size_t)16 * HSLOT, 512, 512, WTh,
        /*e0*/ b1, /*o0*/ HD1, /*o2h*/ nullptr, /*o3h*/ nullptr, /*oh*/ nullptr,
        /*zxp*/ nullptr, /*tgp*/ nullptr, /*Cp*/ nullptr,
        /*inp*/ nullptr, /*WtT*/ nullptr, /*bT*/ nullptr);
    head2_k<<<512, 256>>>(HD1, W2, b2, HD2);
    head3_k<<<16, 256>>>(HD2, W3, b3, out);
}

// round 14
// speedup vs baseline: 1.3466x; 1.0122x over previous
#include <cuda_runtime.h>
#include <cuda_fp16.h>
#include <cuda_fp8.h>
#include <math.h>
#include <stdint.h>

#define Bn 4096
#define HSLOT ((size_t)Bn * 512)
#define STAGE_BYTES 36864
#define SMEM_BYTES (3 * STAGE_BYTES)

// Gate permutation: physical col p (p<2048) <-> logical (gate g, unit j):
//   g = (p>>3)&3, j = ((p>>5)<<3) + (p&7)

// ---------------- device scratch ----------------
__device__ __half g_Ah[(size_t)17 * HSLOT];         // slot j+1 holds h_j (fp16); slot 0 unused
__device__ __half g_APRE[(size_t)65536 * 64];
__device__ __half g_WTb[(size_t)3072 * 512];        // [Uh(perm,2048) | Wa(512) | We(512)], n-major
__device__ __half g_WPRE[(size_t)2560 * 64];
__device__ __half g_WT2[1024 * 512];                // [Wb | Wg]
__device__ __half g_WTh[256 * 512];                 // W1
__device__ __half g_ZX16[(size_t)16 * Bn * 2048];
__device__ __half g_TG16[(size_t)16 * Bn * 512];
__device__ unsigned char g_MEMA8[(size_t)15 * HSLOT];  // slot j: h_j @ Wa, fp8 e4m3
__device__ __half g_HWE16[(size_t)15 * HSLOT];      // slot j: h_j @ We
__device__ __half g_HcH[(size_t)Bn * 512];
__device__ __half g_HBh[(size_t)Bn * 512];
__device__ __half g_HGh[(size_t)Bn * 512];
__device__ float g_C[(size_t)Bn * 512];
__device__ float g_HD1[(size_t)Bn * 256];
__device__ float g_HD2[(size_t)Bn * 32];
__device__ float g_s[512];
__device__ float g_sA[512];
__device__ float g_sWe[512];

__device__ __forceinline__ float sigm(float x) { return 1.f / (1.f + expf(-x)); }
__device__ __forceinline__ float sigmf_(float x) { return __fdividef(1.f, 1.f + __expf(-x)); }
__device__ __forceinline__ float tanh_app(float x) {
    float y; asm("tanh.approx.f32 %0, %1;" : "=f"(y) : "f"(x)); return y;
}

__device__ __forceinline__ uint32_t smem_u32(const void* p) {
    uint32_t a;
    asm("{ .reg .u64 t; cvta.to.shared.u64 t, %1; cvt.u32.u64 %0, t; }" : "=r"(a) : "l"(p));
    return a;
}
__device__ __forceinline__ void ldm4(uint32_t* r, uint32_t a) {
    asm volatile("ldmatrix.sync.aligned.m8n8.x4.shared.b16 {%0,%1,%2,%3}, [%4];"
                 : "=r"(r[0]), "=r"(r[1]), "=r"(r[2]), "=r"(r[3]) : "r"(a));
}
__device__ __forceinline__ void mma16816(float* c, const uint32_t* a, uint32_t b0, uint32_t b1) {
    asm volatile("mma.sync.aligned.m16n8k16.row.col.f32.f16.f16.f32 "
                 "{%0,%1,%2,%3}, {%4,%5,%6,%7}, {%8,%9}, {%0,%1,%2,%3};"
                 : "+f"(c[0]), "+f"(c[1]), "+f"(c[2]), "+f"(c[3])
                 : "r"(a[0]), "r"(a[1]), "r"(a[2]), "r"(a[3]), "r"(b0), "r"(b1));
}
__device__ __forceinline__ void cp16(uint32_t saddr, const void* gptr) {
    asm volatile("cp.async.cg.shared.global [%0], [%1], 16;"
                 :: "r"(saddr), "l"(__cvta_generic_to_global(gptr)) : "memory");
}
__device__ __forceinline__ void cp_commit() {
    asm volatile("cp.async.commit_group;" ::: "memory");
}

// ---------------- prep kernels ----------------
__global__ void prep_weights(const float* __restrict__ Uh, const float* __restrict__ Wx,
                             const float* __restrict__ Wt, const float* __restrict__ Wa,
                             const float* __restrict__ WxT, const float* __restrict__ Wb,
                             const float* __restrict__ Wg, const float* __restrict__ We,
                             const float* __restrict__ W1) {
    int stride = gridDim.x * blockDim.x;
    int t0 = blockIdx.x * blockDim.x + threadIdx.x;
    for (int i = t0; i < 3072 * 512; i += stride) {
        int n = i >> 9, k = i & 511;
        float w;
        if (n < 2048) {
            int g = (n >> 3) & 3, j = ((n >> 5) << 3) + (n & 7);
            w = Uh[(size_t)k * 2048 + g * 512 + j];
        } else if (n < 2560) {
            w = Wa[(size_t)k * 512 + (n - 2048)];
        } else {
            w = We[(size_t)k * 512 + (n - 2560)];
        }
        g_WTb[i] = __float2half(w);
    }
    for (int i = t0; i < 2560 * 64; i += stride) {
        int n = i >> 6, k = i & 63;
        float w;
        if (n < 2048) {
            int g = (n >> 3) & 3, j = ((n >> 5) << 3) + (n & 7);
            if (k < 63) w = Wx[(size_t)k * 2048 + g * 512 + j];
            else        w = (g < 3) ? Wt[g * 512 + j] : 0.f;
        } else {
            w = (k < 63) ? WxT[(size_t)k * 512 + (n - 2048)] : 0.f;
        }
        g_WPRE[i] = __float2half(w);
    }
    for (int i = t0; i < 1024 * 512; i += stride) {
        int n = i >> 9, k = i & 511;
        float w = (n < 512) ? Wb[(size_t)k * 512 + n] : Wg[(size_t)k * 512 + (n - 512)];
        g_WT2[i] = __float2half(w);
    }
    for (int i = t0; i < 256 * 512; i += stride) {
        int n = i >> 9, k = i & 511;
        g_WTh[i] = __float2half(W1[(size_t)k * 256 + n]);
    }
}

__global__ void prep_s(const float* __restrict__ init_proj) {
    int h = threadIdx.x;
    float s = 0.f;
    for (int f = 0; f < 64; ++f) s += init_proj[f * 512 + h];
    g_s[h] = s;
}

__global__ void prep_sA(const float* __restrict__ Wa, const float* __restrict__ We) {
    int h = threadIdx.x;
    float a = 0.f, e = 0.f;
    for (int k = 0; k < 512; ++k) {
        float sv = g_s[k];
        a = fmaf(sv, Wa[k * 512 + h], a);
        e = fmaf(sv, We[k * 512 + h], e);
    }
    g_sA[h] = a;
    g_sWe[h] = e;
}

__global__ void prep_A(const float* __restrict__ inp) {
    int stride = gridDim.x * blockDim.x;
    int t0 = blockIdx.x * blockDim.x + threadIdx.x;
    for (int i = t0; i < 65536 * 64; i += stride) {
        int r = i >> 6, k = i & 63;
        float v = (k < 63) ? inp[(size_t)r * 64 + 1 + k] : inp[(size_t)r * 64];
        g_APRE[i] = __float2half(v);
    }
}

// ---------------- fp16 HMMA GEMM, 3-stage pipeline, 1 sync/chunk ----------------
// MODE 1: N=3072 [Uh(perm)|Wa|We]: n<2048 -> FUSED gates -> C, HcH(oh);
//         2048..2559 -> o2b (MEMA slot, fp8 e4m3); 2560..3071 -> o3h (HWE slot, fp16)
// MODE 2: N=1024 [Wb|Wg]: c<512 -> o2h=HBh(+e0); else oh=HGh
// MODE 4: N=256 W1: o0 = relu(acc+e0)
// MODE 5: N=2560 pre: c<2048 -> ZX16(perm); else TG16
template <int MODE>
__global__ __launch_bounds__(256, 2)
void mma_gemm(const __half* __restrict__ A, int lda, int K,
              const __half* __restrict__ Bh,
              const float* __restrict__ e0,
              float* __restrict__ o0,
              unsigned char* __restrict__ o2b, __half* __restrict__ o3h,
              __half* __restrict__ o2h, __half* __restrict__ oh,
              const __half* __restrict__ zxp, const __half* __restrict__ tgp,
              float* __restrict__ Cp,
              const float* __restrict__ inp, const float* __restrict__ WtT,
              const float* __restrict__ bT) {
    extern __shared__ char smem[];
    uint32_t sb = smem_u32(smem);
    const int tid = threadIdx.x;
    const int lane = tid & 31, wid = tid >> 5;
    const int wm = wid & 1, wn = wid >> 1;
    const int gid = lane >> 2, tq = lane & 3;
    const int m0 = blockIdx.y * 128, n0 = blockIdx.x * 128;

    const int kch = K >> 6;

    float acc[4][4][4];
    #pragma unroll
    for (int a = 0; a < 4; ++a)
        #pragma unroll
        for (int b2 = 0; b2 < 4; ++b2)
            #pragma unroll
            for (int c = 0; c < 4; ++c) acc[a][b2][c] = 0.f;

    auto copy_chunk = [&](int ch, int s) {
        int kc = ch << 6;
        uint32_t base = sb + s * STAGE_BYTES;
        #pragma unroll
        for (int i = 0; i < 4; ++i) {
            int lin = tid + (i << 8);
            int r = lin >> 3;
            int c16 = (lin & 7) << 4;
            cp16(base + r * 144 + c16,
                 (const char*)(A + (size_t)(m0 + r) * lda + kc) + c16);
            cp16(base + 18432 + r * 144 + c16,
                 (const char*)(Bh + (size_t)(n0 + r) * K + kc) + c16);
        }
    };

    copy_chunk(0, 0);
    cp_commit();
    if (kch > 1) { copy_chunk(1, 1); cp_commit(); }

    const int arow = wm * 64 + (lane & 15);
    const int acol = (lane >> 4) << 4;
    const int brow = wn * 32 + (lane & 7) + ((lane >> 4) << 3);
    const int bcol = ((lane >> 3) & 1) << 4;

    for (int ch = 0; ch < kch; ++ch) {
        if (ch + 1 < kch) {
            asm volatile("cp.async.wait_group 1;" ::: "memory");
        } else {
            asm volatile("cp.async.wait_group 0;" ::: "memory");
        }
        __syncthreads();

        int buf = ch % 3;
        uint32_t abase = sb + buf * STAGE_BYTES;
        uint32_t bbase = abase + 18432;
        #pragma unroll
        for (int k16 = 0; k16 < 4; ++k16) {
            int kb = k16 << 5;
            uint32_t bf[2][4];
            #pragma unroll
            for (int ni2 = 0; ni2 < 2; ++ni2)
                ldm4(bf[ni2], bbase + (brow + ni2 * 16) * 144 + kb + bcol);
            uint32_t af[4][4];
            #pragma unroll
            for (int mi = 0; mi < 4; ++mi)
                ldm4(af[mi], abase + (arow + mi * 16) * 144 + kb + acol);
            #pragma unroll
            for (int ni2 = 0; ni2 < 2; ++ni2)
                #pragma unroll
                for (int mi = 0; mi < 4; ++mi) {
                    mma16816(acc[mi][ni2 * 2],     af[mi], bf[ni2][0], bf[ni2][1]);
                    mma16816(acc[mi][ni2 * 2 + 1], af[mi], bf[ni2][2], bf[ni2][3]);
                }
        }
        if (ch + 2 < kch) {
            copy_chunk(ch + 2, (ch + 2) % 3);
            cp_commit();
        }
    }

    // ---- epilogues ----
    if (MODE == 1) {
        if (n0 < 2048) {
            int blk = (n0 + wn * 32) >> 5;
            int j = blk * 8 + (tq << 1);
            #pragma unroll
            for (int mi = 0; mi < 4; ++mi) {
                int mb = m0 + wm * 64 + mi * 16 + gid;
                #pragma unroll
                for (int hf = 0; hf < 2; ++hf) {
                    int r = mb + hf * 8;
                    int ko = hf * 2;
                    const __half* zxr = zxp + (size_t)r * 2048 + blk * 32 + (tq << 1);
                    float2 xi = __half22float2(*(const __half2*)(zxr));
                    float2 xf = __half22float2(*(const __half2*)(zxr + 8));
                    float2 xo = __half22float2(*(const __half2*)(zxr + 16));
                    float2 xc = __half22float2(*(const __half2*)(zxr + 24));
                    float2 tg2 = __half22float2(*(const __half2*)(tgp + (size_t)r * 512 + j));
                    float2 cold = *(float2*)(Cp + (size_t)r * 512 + j);
                    float ch0 = tanh_app(acc[mi][3][ko] + xc.x);
                    float ch1 = tanh_app(acc[mi][3][ko + 1] + xc.y);
                    float c0 = fmaf(sigmf_(acc[mi][1][ko] + xf.x), cold.x,
                                    (sigmf_(acc[mi][0][ko] + xi.x) + tg2.x) * ch0);
                    float c1 = fmaf(sigmf_(acc[mi][1][ko + 1] + xf.y), cold.y,
                                    (sigmf_(acc[mi][0][ko + 1] + xi.y) + tg2.y) * ch1);
                    *(float2*)(Cp + (size_t)r * 512 + j) = make_float2(c0, c1);
                    float h0 = sigmf_(acc[mi][2][ko] + xo.x) * tanh_app(c0);
                    float h1 = sigmf_(acc[mi][2][ko + 1] + xo.y) * tanh_app(c1);
                    *(__half2*)(oh + (size_t)r * 512 + j) = __floats2half2_rn(h0, h1);
                }
            }
        } else if (n0 < 2560) {
            // MEMA slot, fp8 e4m3
            #pragma unroll
            for (int mi = 0; mi < 4; ++mi)
                #pragma unroll
                for (int ni = 0; ni < 4; ++ni) {
                    float* cc = acc[mi][ni];
                    int m = m0 + wm * 64 + mi * 16 + gid;
                    int c = n0 + wn * 32 + ni * 8 + (tq << 1) - 2048;
                    __nv_fp8x2_storage_t p0 = __nv_cvt_float2_to_fp8x2(
                        make_float2(cc[0], cc[1]), __NV_SATFINITE, __NV_E4M3);
                    __nv_fp8x2_storage_t p1 = __nv_cvt_float2_to_fp8x2(
                        make_float2(cc[2], cc[3]), __NV_SATFINITE, __NV_E4M3);
                    *(__nv_fp8x2_storage_t*)(o2b + (size_t)m * 512 + c) = p0;
                    *(__nv_fp8x2_storage_t*)(o2b + (size_t)(m + 8) * 512 + c) = p1;
                }
        } else {
            #pragma unroll
            for (int mi = 0; mi < 4; ++mi)
                #pragma unroll
                for (int ni = 0; ni < 4; ++ni) {
                    float* cc = acc[mi][ni];
                    int m = m0 + wm * 64 + mi * 16 + gid;
                    int c = n0 + wn * 32 + ni * 8 + (tq << 1) - 2560;
                    *(__half2*)(o3h + (size_t)m * 512 + c) = __floats2half2_rn(cc[0], cc[1]);
                    *(__half2*)(o3h + (size_t)(m + 8) * 512 + c) = __floats2half2_rn(cc[2], cc[3]);
                }
        }
        return;
    }

    auto epi = [&](int m, int c, float x, float y) {
        if (MODE == 2) {
            if (c < 512) {
                *(__half2*)(o2h + (size_t)m * 512 + c) =
                    __floats2half2_rn(x + e0[c], y + e0[c + 1]);
            } else {
                *(__half2*)(oh + (size_t)m * 512 + (c - 512)) = __floats2half2_rn(x, y);
            }
        } else if (MODE == 4) {
            *(float2*)(o0 + (size_t)m * 256 + c) =
                make_float2(fmaxf(x + e0[c], 0.f), fmaxf(y + e0[c + 1], 0.f));
        } else {  // MODE 5
            int b_ = m >> 4, t_ = m & 15;
            size_t zr = (size_t)t_ * Bn + b_;
            if (c < 2048) {
                int g = (c >> 3) & 3;
                int j0 = ((c >> 5) << 3) + (c & 7);
                *(__half2*)(g_ZX16 + zr * 2048 + c) =
                    __floats2half2_rn(x + e0[g * 512 + j0], y + e0[g * 512 + j0 + 1]);
            } else {
                int j = c - 2048;
                float tv = inp[(size_t)m * 64];
                float t0v = sigm(x + sigm(tv * WtT[j]) + bT[j]);
                float t1v = sigm(y + sigm(tv * WtT[j + 1]) + bT[j + 1]);
                *(__half2*)(g_TG16 + zr * 512 + j) = __floats2half2_rn(t0v, t1v);
            }
        }
    };

    #pragma unroll
    for (int mi = 0; mi < 4; ++mi) {
        #pragma unroll
        for (int ni = 0; ni < 4; ++ni) {
            float* cc = acc[mi][ni];
            int m = m0 + wm * 64 + mi * 16 + gid;
            int c = n0 + wn * 32 + ni * 8 + (tq << 1);
            epi(m, c, cc[0], cc[1]);
            epi(m + 8, c, cc[2], cc[3]);
        }
    }
}

// ---------------- t=0 gates ----------------
__global__ void gates0_k(const __half* __restrict__ ZX, const __half* __restrict__ TG,
                         float* __restrict__ C, __half* __restrict__ HcH) {
    int idx = blockIdx.x * blockDim.x + threadIdx.x;
    int b = idx >> 9, j = idx & 511;
    int blk = j >> 3, jr = j & 7;
    const __half* zx = ZX + (size_t)b * 2048 + blk * 32 + jr;
    float zi = __half2float(zx[0]);
    float zo = __half2float(zx[16]);
    float zc = __half2float(zx[24]);
    float tg = __half2float(TG[idx]);
    float ch = tanh_app(zc);
    float c = (sigmf_(zi) + tg) * ch;
    C[idx] = c;
    HcH[idx] = __float2half(sigmf_(zo) * tanh_app(c));
}

// ---------------- attention + h_new epilogue (fp8 MEMA, fp16 HWE) ----------------
__global__ void __launch_bounds__(256) attn_k(const __half* __restrict__ HB,
                                              const __half* __restrict__ HG,
                                              const float* __restrict__ va,
                                              const float* __restrict__ bhv,
                                              __half* __restrict__ AhNext, int t) {
    int b = blockIdx.x, tid = threadIdx.x;
    __shared__ float sred[15][8];
    __shared__ float se[15];
    float2 hb = __half22float2(((const __half2*)(HB + (size_t)b * 512))[tid]);
    float2 va2 = *(const float2*)(va + 2 * tid);
    float2 sA2 = *(const float2*)(g_sA + 2 * tid);
    float2 sW2 = *(const float2*)(g_sWe + 2 * tid);
    int lane = tid & 31, wp = tid >> 5;

    #pragma unroll
    for (int d = 0; d < 15; ++d) {
        int j = t - 15 + d;
        float m0, m1;
        if (j < 0) {
            m0 = sA2.x; m1 = sA2.y;
        } else {
            __nv_fp8x2_storage_t raw =
                ((const __nv_fp8x2_storage_t*)(g_MEMA8 + (size_t)j * HSLOT + (size_t)b * 512))[tid];
            __half2_raw hr = __nv_cvt_fp8x2_to_halfraw2(raw, __NV_E4M3);
            float2 f = __half22float2(*(__half2*)&hr);
            m0 = f.x; m1 = f.y;
        }
        float s = va2.x * tanh_app(m0 + hb.x) + va2.y * tanh_app(m1 + hb.y);
        #pragma unroll
        for (int off = 16; off; off >>= 1) s += __shfl_xor_sync(0xffffffffu, s, off);
        if (lane == 0) sred[d][wp] = s;
    }
    __syncthreads();
    if (tid < 15) {
        float e = 0.f;
        #pragma unroll
        for (int w2 = 0; w2 < 8; ++w2) e += sred[tid][w2];
        se[tid] = e;
    }
    __syncthreads();

    float mx = -1e30f;
    #pragma unroll
    for (int d = 0; d < 15; ++d) mx = fmaxf(mx, se[d]);
    float al[15], sum = 0.f;
    #pragma unroll
    for (int d = 0; d < 15; ++d) { al[d] = __expf(se[d] - mx); sum += al[d]; }
    float inv = __fdividef(1.f, sum);
    float c0 = 0.f, c1 = 0.f;
    #pragma unroll
    for (int d = 0; d < 15; ++d) {
        int j = t - 15 + d;
        float a = al[d] * inv;
        float m0, m1;
        if (j < 0) {
            m0 = sW2.x; m1 = sW2.y;
        } else {
            float2 f = __half22float2(
                ((const __half2*)(g_HWE16 + (size_t)j * HSLOT + (size_t)b * 512))[tid]);
            m0 = f.x; m1 = f.y;
        }
        c0 = fmaf(a, m0, c0);
        c1 = fmaf(a, m1, c1);
    }
    float2 hg = __half22float2(((const __half2*)(HG + (size_t)b * 512))[tid]);
    float2 bh2 = *(const float2*)(bhv + 2 * tid);
    float h0 = tanh_app(c0 + hg.x + bh2.x);
    float h1 = tanh_app(c1 + hg.y + bh2.y);
    ((__half2*)(AhNext + (size_t)b * 512))[tid] = __floats2half2_rn(h0, h1);
}

// ---------------- head layers 2,3 ----------------
__global__ void head2_k(const float* __restrict__ HD1, const float* __restrict__ W2,
                        const float* __restrict__ b2, float* __restrict__ HD2) {
    int warp = (blockIdx.x * blockDim.x + threadIdx.x) >> 5;
    int lane = threadIdx.x & 31;
    if (warp >= Bn) return;
    const float* h = HD1 + (size_t)warp * 256;
    float acc = 0.f;
    for (int k = 0; k < 256; ++k) acc = fmaf(h[k], W2[k * 32 + lane], acc);
    HD2[(size_t)warp * 32 + lane] = fmaxf(acc + b2[lane], 0.f);
}

__global__ void head3_k(const float* __restrict__ HD2, const float* __restrict__ W3,
                        const float* __restrict__ b3, float* __restrict__ out) {
    int b = blockIdx.x * blockDim.x + threadIdx.x;
    if (b >= Bn) return;
    float a0 = b3[0], a1 = b3[1];
    const float* h = HD2 + (size_t)b * 32;
    #pragma unroll
    for (int k = 0; k < 32; ++k) {
        float hv = h[k];
        a0 = fmaf(hv, W3[k * 2 + 0], a0);
        a1 = fmaf(hv, W3[k * 2 + 1], a1);
    }
    float m = fmaxf(a0, a1);
    float e0v = expf(a0 - m), e1v = expf(a1 - m);
    float inv = 1.f / (e0v + e1v);
    out[(size_t)b * 2 + 0] = e0v * inv;
    out[(size_t)b * 2 + 1] = e1v * inv;
}

// ---------------- launcher ----------------
extern "C" void kernel_launch(void* const* d_in, const int* in_sizes, int n_in,
                              void* d_out, int out_size) {
    const float* inputs    = (const float*)d_in[0];
    const float* init_proj = (const float*)d_in[1];
    const float* Wx  = (const float*)d_in[3];
    const float* Uh  = (const float*)d_in[4];
    const float* Wt  = (const float*)d_in[5];
    const float* b   = (const float*)d_in[6];
    const float* WxT = (const float*)d_in[7];
    const float* WtT = (const float*)d_in[8];
    const float* bT  = (const float*)d_in[9];
    const float* Wa  = (const float*)d_in[10];
    const float* Wb  = (const float*)d_in[11];
    const float* va  = (const float*)d_in[12];
    const float* ba  = (const float*)d_in[13];
    const float* We  = (const float*)d_in[14];
    const float* Wg  = (const float*)d_in[15];
    const float* bh  = (const float*)d_in[16];
    const float* W1  = (const float*)d_in[17];
    const float* b1  = (const float*)d_in[18];
    const float* W2  = (const float*)d_in[19];
    const float* b2  = (const float*)d_in[20];
    const float* W3  = (const float*)d_in[21];
    const float* b3  = (const float*)d_in[22];
    float* out = (float*)d_out;

    cudaFuncSetAttribute(mma_gemm<1>, cudaFuncAttributeMaxDynamicSharedMemorySize, SMEM_BYTES);
    cudaFuncSetAttribute(mma_gemm<2>, cudaFuncAttributeMaxDynamicSharedMemorySize, SMEM_BYTES);
    cudaFuncSetAttribute(mma_gemm<4>, cudaFuncAttributeMaxDynamicSharedMemorySize, SMEM_BYTES);
    cudaFuncSetAttribute(mma_gemm<5>, cudaFuncAttributeMaxDynamicSharedMemorySize, SMEM_BYTES);

    __half *Ah, *APRE, *WTb, *WPRE, *WT2, *WTh, *HWE16, *ZX16, *TG16, *HcH, *HBh, *HGh;
    unsigned char* MEMA8;
    float *C, *HD1, *HD2;
    cudaGetSymbolAddress((void**)&Ah, g_Ah);
    cudaGetSymbolAddress((void**)&APRE, g_APRE);
    cudaGetSymbolAddress((void**)&WTb, g_WTb);
    cudaGetSymbolAddress((void**)&WPRE, g_WPRE);
    cudaGetSymbolAddress((void**)&WT2, g_WT2);
    cudaGetSymbolAddress((void**)&WTh, g_WTh);
    cudaGetSymbolAddress((void**)&MEMA8, g_MEMA8);
    cudaGetSymbolAddress((void**)&HWE16, g_HWE16);
    cudaGetSymbolAddress((void**)&ZX16, g_ZX16);
    cudaGetSymbolAddress((void**)&TG16, g_TG16);
    cudaGetSymbolAddress((void**)&HcH, g_HcH);
    cudaGetSymbolAddress((void**)&HBh, g_HBh);
    cudaGetSymbolAddress((void**)&HGh, g_HGh);
    cudaGetSymbolAddress((void**)&C, g_C);
    cudaGetSymbolAddress((void**)&HD1, g_HD1);
    cudaGetSymbolAddress((void**)&HD2, g_HD2);

    prep_weights<<<1024, 256>>>(Uh, Wx, Wt, Wa, WxT, Wb, Wg, We, W1);
    prep_s<<<1, 512>>>(init_proj);
    prep_sA<<<1, 512>>>(Wa, We);
    prep_A<<<2048, 256>>>(inputs);

    // pre-GEMM: ZX(perm) + TG for all steps
    mma_gemm<5><<<dim3(20, 512), 256, SMEM_BYTES>>>(
        APRE, 64, 64, WPRE,
        /*e0*/ b, /*o0*/ nullptr,
        /*o2b*/ nullptr, /*o3h*/ nullptr, /*o2h*/ nullptr, /*oh*/ nullptr,
        /*zxp*/ nullptr, /*tgp*/ nullptr, /*Cp*/ nullptr,
        /*inp*/ inputs, /*WtT*/ WtT, /*bT*/ bT);

    for (int t = 0; t < 16; ++t) {
        if (t > 0) {
            // h_{t-1} @ [Uh|Wa|We] + fused gates -> HcH, C, MEMA8/HWE slot t-1
            mma_gemm<1><<<dim3(24, 32), 256, SMEM_BYTES>>>(
                Ah + (size_t)t * HSLOT, 512, 512, WTb,
                /*e0*/ nullptr, /*o0*/ nullptr,
                /*o2b*/ MEMA8 + (size_t)(t - 1) * HSLOT,
                /*o3h*/ HWE16 + (size_t)(t - 1) * HSLOT,
                /*o2h*/ nullptr, /*oh*/ HcH,
                /*zxp*/ ZX16 + (size_t)t * Bn * 2048, /*tgp*/ TG16 + (size_t)t * Bn * 512,
                /*Cp*/ C,
                /*inp*/ nullptr, /*WtT*/ nullptr, /*bT*/ nullptr);
        } else {
            gates0_k<<<8192, 256>>>(ZX16, TG16, C, HcH);
        }
        mma_gemm<2><<<dim3(8, 32), 256, SMEM_BYTES>>>(
            HcH, 512, 512, WT2,
            /*e0*/ ba, /*o0*/ nullptr,
            /*o2b*/ nullptr, /*o3h*/ nullptr, /*o2h*/ HBh, /*oh*/ HGh,
            /*zxp*/ nullptr, /*tgp*/ nullptr, /*Cp*/ nullptr,
            /*inp*/ nullptr, /*WtT*/ nullptr, /*bT*/ nullptr);
        attn_k<<<4096, 256>>>(HBh, HGh, va, bh, Ah + (size_t)(t + 1) * HSLOT, t);
    }

    mma_gemm<4><<<dim3(2, 32), 256, SMEM_BYTES>>>(
        Ah + (size_t)16 * HSLOT, 512, 512, WTh,
        /*e0*/ b1, /*o0*/ HD1,
        /*o2b*/ nullptr, /*o3h*/ nullptr, /*o2h*/ nullptr, /*oh*/ nullptr,
        /*zxp*/ nullptr, /*tgp*/ nullptr, /*Cp*/ nullptr,
        /*inp*/ nullptr, /*WtT*/ nullptr, /*bT*/ nullptr);
    head2_k<<<512, 256>>>(HD1, W2, b2, HD2);
    head3_k<<<16, 256>>>(HD2, W3, b3, out);
}